// round 5
// baseline (speedup 1.0000x reference)
#include <cuda_runtime.h>
#include <cuda_bf16.h>
#include <math.h>

// Problem constants: x[N=2, T=16, S=256, D=1024]
// qkv = x @ Wqkv[D, 3D]; split into 6 chunks of 512; heads=8, Dh=64, scale=0.125
// spatial attn over S per (n,t,h); temporal attn over T per (n,s,h)
// out = concat(x_s, x_t) @ Wproj + bproj

#define NB 2
#define TB 16
#define SB 256
#define DB 1024
#define ROWS (NB*TB*SB)      // 8192
#define THREE_D (3*DB)       // 3072
#define HEADS 8
#define DH 64

// Scratch (device globals: allocation-free per harness rules)
__device__ float g_qkv[(size_t)ROWS * THREE_D];   // ~100.7 MB
__device__ float g_attn[(size_t)ROWS * DB];       // ~33.5 MB

// ---------------------------------------------------------------------------
// Classic blocked SGEMM: C[M,N] = A[M,K] @ B[K,N] (+bias), row-major.
// BM=BN=128, BK=8, 256 threads, 8x8 register tile per thread.
// Inner loop uses LDS.128 (float4) for both fragments.
// ---------------------------------------------------------------------------
template<bool BIAS>
__global__ __launch_bounds__(256) void sgemm128(
    const float* __restrict__ A, const float* __restrict__ B,
    const float* __restrict__ bias, float* __restrict__ C,
    int M, int N, int K)
{
    constexpr int BM = 128, BN = 128, BK = 8, TM = 8, TN = 8;
    __shared__ float As[BK][BM];
    __shared__ float Bs[BK][BN];

    const int tid = threadIdx.x;
    const int bx = blockIdx.x;   // N tile
    const int by = blockIdx.y;   // M tile
    const int tx = tid & 15;     // 0..15
    const int ty = tid >> 4;     // 0..15

    // A-tile load mapping: 128 rows x 8 cols, one float4 per thread
    const int aRow = tid >> 1;           // 0..127
    const int aCol = (tid & 1) * 4;      // 0 or 4
    // B-tile load mapping: 8 rows x 128 cols, one float4 per thread
    const int bRow = tid >> 5;           // 0..7
    const int bCol = (tid & 31) * 4;     // 0..124

    const float* Aptr = A + (size_t)(by * BM) * K;
    const float* Bptr = B + bx * BN;

    float acc[TM][TN];
    #pragma unroll
    for (int i = 0; i < TM; i++)
        #pragma unroll
        for (int j = 0; j < TN; j++) acc[i][j] = 0.f;

    for (int k0 = 0; k0 < K; k0 += BK) {
        float4 a4 = *(const float4*)(Aptr + (size_t)aRow * K + k0 + aCol);
        As[aCol + 0][aRow] = a4.x;
        As[aCol + 1][aRow] = a4.y;
        As[aCol + 2][aRow] = a4.z;
        As[aCol + 3][aRow] = a4.w;
        float4 b4 = *(const float4*)(Bptr + (size_t)(k0 + bRow) * N + bCol);
        *(float4*)&Bs[bRow][bCol] = b4;
        __syncthreads();

        #pragma unroll
        for (int kk = 0; kk < BK; kk++) {
            float4 a0 = *(const float4*)&As[kk][ty * TM + 0];
            float4 a1 = *(const float4*)&As[kk][ty * TM + 4];
            float4 b0 = *(const float4*)&Bs[kk][tx * TN + 0];
            float4 b1 = *(const float4*)&Bs[kk][tx * TN + 4];
            float ar[TM] = {a0.x, a0.y, a0.z, a0.w, a1.x, a1.y, a1.z, a1.w};
            float br[TN] = {b0.x, b0.y, b0.z, b0.w, b1.x, b1.y, b1.z, b1.w};
            #pragma unroll
            for (int i = 0; i < TM; i++)
                #pragma unroll
                for (int j = 0; j < TN; j++)
                    acc[i][j] = fmaf(ar[i], br[j], acc[i][j]);
        }
        __syncthreads();
    }

    #pragma unroll
    for (int i = 0; i < TM; i++) {
        const int row = by * BM + ty * TM + i;
        float* Crow = C + (size_t)row * N + bx * BN + tx * TN;
        #pragma unroll
        for (int j4 = 0; j4 < TN / 4; j4++) {
            float4 o;
            o.x = acc[i][j4 * 4 + 0];
            o.y = acc[i][j4 * 4 + 1];
            o.z = acc[i][j4 * 4 + 2];
            o.w = acc[i][j4 * 4 + 3];
            if (BIAS) {
                const float* bp = bias + bx * BN + tx * TN + j4 * 4;
                o.x += bp[0]; o.y += bp[1]; o.z += bp[2]; o.w += bp[3];
            }
            *(float4*)(Crow + j4 * 4) = o;
        }
    }
}

// ---------------------------------------------------------------------------
// Spatial attention: one block per (n*t, head). 256 threads, 1 query each.
// K/V tiles (256 x 64 each) staged in 128 KB dynamic smem. Online softmax.
//   q_s cols [0,512), k_s cols [1024,1536), v_s cols [2048,2560)
//   output -> g_attn cols [0,512)
// ---------------------------------------------------------------------------
__global__ __launch_bounds__(256) void spatial_attn(
    const float* __restrict__ qkv, float* __restrict__ out)
{
    extern __shared__ float sm[];
    float* Ks = sm;             // [256][64]
    float* Vs = sm + 256 * 64;  // [256][64]

    const int inst = blockIdx.x;     // 0..255
    const int h = inst & 7;
    const int nt = inst >> 3;        // 0..31
    const int tid = threadIdx.x;     // query index s

    const float* base = qkv + (size_t)nt * SB * THREE_D;

    // Cooperative K/V load (float4 granularity)
    for (int i = tid; i < 256 * 16; i += 256) {
        const int row = i >> 4;
        const int c4 = (i & 15) << 2;
        const float* rb = base + (size_t)row * THREE_D + h * DH;
        *(float4*)(Ks + row * DH + c4) = *(const float4*)(rb + 1024 + c4);
        *(float4*)(Vs + row * DH + c4) = *(const float4*)(rb + 2048 + c4);
    }

    // Per-thread query row (q_s)
    float q[DH];
    {
        const float* qp = base + (size_t)tid * THREE_D + h * DH;
        #pragma unroll
        for (int d4 = 0; d4 < 16; d4++) {
            float4 t = *(const float4*)(qp + d4 * 4);
            q[d4 * 4 + 0] = t.x; q[d4 * 4 + 1] = t.y;
            q[d4 * 4 + 2] = t.z; q[d4 * 4 + 3] = t.w;
        }
    }
    __syncthreads();

    const float scale = 0.125f;  // (D/NUM_HEADS)^-0.5 = 64^-0.5
    float m = -INFINITY, l = 0.f;
    float acc[DH];
    #pragma unroll
    for (int d = 0; d < DH; d++) acc[d] = 0.f;

    for (int j = 0; j < SB; j++) {
        const float* kj = Ks + j * DH;
        float s = 0.f;
        #pragma unroll
        for (int d = 0; d < DH; d++) s = fmaf(q[d], kj[d], s);
        s *= scale;
        const float mn = fmaxf(m, s);
        const float c = __expf(m - mn);   // 0 on first iter (m=-inf)
        const float p = __expf(s - mn);
        l = l * c + p;
        m = mn;
        const float* vj = Vs + j * DH;
        #pragma unroll
        for (int d = 0; d < DH; d++) acc[d] = fmaf(acc[d], c, p * vj[d]);
    }

    const float inv = 1.f / l;
    float* op = out + ((size_t)nt * SB + tid) * DB + h * DH;  // cols [0,512)
    #pragma unroll
    for (int d4 = 0; d4 < 16; d4++) {
        float4 o;
        o.x = acc[d4 * 4 + 0] * inv; o.y = acc[d4 * 4 + 1] * inv;
        o.z = acc[d4 * 4 + 2] * inv; o.w = acc[d4 * 4 + 3] * inv;
        *(float4*)(op + d4 * 4) = o;
    }
}

// ---------------------------------------------------------------------------
// Temporal attention: one block per (n, s). 128 threads: tid = t*8 + h.
// K_t/V_t for all 16 frames (16 x 512 each) staged in 64 KB smem.
// 16 scores per thread live in registers -> exact 2-pass softmax.
//   q_t cols [512,1024), k_t cols [1536,2048), v_t cols [2560,3072)
//   output -> g_attn cols [512,1024)
// ---------------------------------------------------------------------------
__global__ __launch_bounds__(128) void temporal_attn(
    const float* __restrict__ qkv, float* __restrict__ out)
{
    extern __shared__ float sm[];
    float* Ks = sm;              // [16][512]
    float* Vs = sm + 16 * 512;   // [16][512]

    const int ns = blockIdx.x;          // 0..511
    const int n = ns >> 8;
    const int s = ns & 255;
    const int tid = threadIdx.x;
    const int h = tid & 7;
    const int t = tid >> 3;             // 0..15

    const size_t tstride = (size_t)SB * THREE_D;
    const float* rowbase = qkv + ((size_t)(n * TB) * SB + s) * THREE_D;

    // Cooperative K_t / V_t load: 16 rows x 512 cols each
    for (int i = tid; i < 16 * 128; i += 128) {   // float4 count per array
        const int row = i >> 7;
        const int c4 = (i & 127) << 2;
        const float* rb = rowbase + row * tstride;
        *(float4*)(Ks + row * 512 + c4) = *(const float4*)(rb + 1536 + c4);
        *(float4*)(Vs + row * 512 + c4) = *(const float4*)(rb + 2560 + c4);
    }

    // Per-thread query (q_t for frame t, head h)
    float q[DH];
    {
        const float* qp = rowbase + t * tstride + 512 + h * DH;
        #pragma unroll
        for (int d4 = 0; d4 < 16; d4++) {
            float4 v = *(const float4*)(qp + d4 * 4);
            q[d4 * 4 + 0] = v.x; q[d4 * 4 + 1] = v.y;
            q[d4 * 4 + 2] = v.z; q[d4 * 4 + 3] = v.w;
        }
    }
    __syncthreads();

    const float scale = 0.125f;
    float sc[TB];
    float mmax = -INFINITY;
    #pragma unroll
    for (int j = 0; j < TB; j++) {
        const float* kj = Ks + j * 512 + h * DH;
        float d0 = 0.f;
        #pragma unroll
        for (int d = 0; d < DH; d++) d0 = fmaf(q[d], kj[d], d0);
        sc[j] = d0 * scale;
        mmax = fmaxf(mmax, sc[j]);
    }
    float lsum = 0.f;
    #pragma unroll
    for (int j = 0; j < TB; j++) {
        sc[j] = __expf(sc[j] - mmax);
        lsum += sc[j];
    }
    const float inv = 1.f / lsum;

    float acc[DH];
    #pragma unroll
    for (int d = 0; d < DH; d++) acc[d] = 0.f;
    #pragma unroll
    for (int j = 0; j < TB; j++) {
        const float p = sc[j];
        const float* vj = Vs + j * 512 + h * DH;
        #pragma unroll
        for (int d = 0; d < DH; d++) acc[d] = fmaf(p, vj[d], acc[d]);
    }

    float* op = out + ((size_t)(n * TB + t) * SB + s) * DB + 512 + h * DH;
    #pragma unroll
    for (int d4 = 0; d4 < 16; d4++) {
        float4 o;
        o.x = acc[d4 * 4 + 0] * inv; o.y = acc[d4 * 4 + 1] * inv;
        o.z = acc[d4 * 4 + 2] * inv; o.w = acc[d4 * 4 + 3] * inv;
        *(float4*)(op + d4 * 4) = o;
    }
}

// ---------------------------------------------------------------------------
extern "C" void kernel_launch(void* const* d_in, const int* in_sizes, int n_in,
                              void* d_out, int out_size)
{
    const float* x     = (const float*)d_in[0];  // [2,16,256,1024]
    const float* Wqkv  = (const float*)d_in[1];  // [1024,3072]
    const float* Wproj = (const float*)d_in[2];  // [1024,1024]
    const float* bproj = (const float*)d_in[3];  // [1024]
    float* out = (float*)d_out;

    float* qkv_ptr = nullptr;
    float* attn_ptr = nullptr;
    cudaGetSymbolAddress((void**)&qkv_ptr, g_qkv);
    cudaGetSymbolAddress((void**)&attn_ptr, g_attn);

    // Opt-in to >48KB dynamic smem for attention kernels
    cudaFuncSetAttribute(spatial_attn,
        cudaFuncAttributeMaxDynamicSharedMemorySize, 2 * 256 * DH * 4);
    cudaFuncSetAttribute(temporal_attn,
        cudaFuncAttributeMaxDynamicSharedMemorySize, 2 * 16 * 512 * 4);

    // 1) qkv = x @ Wqkv : [8192,1024] x [1024,3072]
    {
        dim3 grid(THREE_D / 128, ROWS / 128);
        sgemm128<false><<<grid, 256>>>(x, Wqkv, nullptr, qkv_ptr,
                                       ROWS, THREE_D, DB);
    }

    // 2) spatial attention: 256 instances (n*t, head)
    spatial_attn<<<NB * TB * HEADS, 256, 2 * 256 * DH * 4>>>(qkv_ptr, attn_ptr);

    // 3) temporal attention: 512 blocks (n, s)
    temporal_attn<<<NB * SB, 128, 2 * 16 * 512 * 4>>>(qkv_ptr, attn_ptr);

    // 4) out = attn @ Wproj + bproj : [8192,1024] x [1024,1024]
    {
        dim3 grid(DB / 128, ROWS / 128);
        sgemm128<true><<<grid, 256>>>(attn_ptr, Wproj, bproj, out,
                                      ROWS, DB, DB);
    }
}

// round 7
// speedup vs baseline: 1.6507x; 1.6507x over previous
#include <cuda_runtime.h>
#include <cuda_bf16.h>
#include <math.h>
#include <stdint.h>

// Problem: x[N=2,T=16,S=256,D=1024]
// qkv = x @ Wqkv[1024,3072]; heads=8, Dh=64, scale=0.125
// spatial attn over S per (n,t,h); temporal attn over T per (n,s,h)
// out = concat(x_s, x_t) @ Wproj + bproj

#define NB 2
#define TB 16
#define SB 256
#define DB 1024
#define ROWS (NB*TB*SB)      // 8192
#define THREE_D (3*DB)       // 3072
#define HEADS 8
#define DH 64

__device__ float g_qkv[(size_t)ROWS * THREE_D];   // ~100.7 MB
__device__ float g_attn[(size_t)ROWS * DB];       // ~33.5 MB

// ---------------------------------------------------------------------------
// Tensor-core GEMM via 3x bf16 split: C = A@B (+bias), fp32 in/out.
// C ~= Ah@Bh + Ah@Bl + Al@Bh  (fp32 accum), error ~2^-18.
// BM=BN=128, BK=32, 256 threads = 8 warps (4m x 2n), each warp 32m x 64n.
// mma.sync.m16n8k16 bf16, ldmatrix-fed fragments.
// ---------------------------------------------------------------------------
__device__ __forceinline__ uint32_t sm_u32(const void* p) {
    return (uint32_t)__cvta_generic_to_shared(p);
}

__device__ __forceinline__ void ldsm_x4(uint32_t* r, uint32_t addr) {
    asm volatile("ldmatrix.sync.aligned.m8n8.x4.shared.b16 {%0,%1,%2,%3}, [%4];"
                 : "=r"(r[0]), "=r"(r[1]), "=r"(r[2]), "=r"(r[3]) : "r"(addr));
}
__device__ __forceinline__ void ldsm_x4_t(uint32_t* r, uint32_t addr) {
    asm volatile("ldmatrix.sync.aligned.m8n8.x4.trans.shared.b16 {%0,%1,%2,%3}, [%4];"
                 : "=r"(r[0]), "=r"(r[1]), "=r"(r[2]), "=r"(r[3]) : "r"(addr));
}
__device__ __forceinline__ void mma16816(float* c, const uint32_t* a,
                                         const uint32_t* b) {
    asm volatile(
        "mma.sync.aligned.m16n8k16.row.col.f32.bf16.bf16.f32 "
        "{%0,%1,%2,%3}, {%4,%5,%6,%7}, {%8,%9}, {%0,%1,%2,%3};"
        : "+f"(c[0]), "+f"(c[1]), "+f"(c[2]), "+f"(c[3])
        : "r"(a[0]), "r"(a[1]), "r"(a[2]), "r"(a[3]), "r"(b[0]), "r"(b[1]));
}

__device__ __forceinline__ void split2(float v, uint16_t& hi, uint16_t& lo) {
    __nv_bfloat16 h = __float2bfloat16(v);
    __nv_bfloat16 l = __float2bfloat16(v - __bfloat162float(h));
    hi = __bfloat16_as_ushort(h);
    lo = __bfloat16_as_ushort(l);
}

template<bool BIAS>
__global__ __launch_bounds__(256, 1) void gemm_bf16x3(
    const float* __restrict__ A, const float* __restrict__ B,
    const float* __restrict__ bias, float* __restrict__ C,
    int M, int N, int K)
{
    // Padded rows keep ldmatrix conflict-free (A: 40*2=80B, B: 136*2=272B).
    __shared__ __align__(16) __nv_bfloat16 As_hi[128][40];
    __shared__ __align__(16) __nv_bfloat16 As_lo[128][40];
    __shared__ __align__(16) __nv_bfloat16 Bs_hi[32][136];
    __shared__ __align__(16) __nv_bfloat16 Bs_lo[32][136];

    const int tid  = threadIdx.x;
    const int lane = tid & 31;
    const int warp = tid >> 5;
    const int wm = warp & 3;        // 0..3  -> m offset 32*wm
    const int wn = warp >> 2;       // 0..1  -> n offset 64*wn
    const int m_base = wm * 32;
    const int n_base = wn * 64;
    const int blockM = blockIdx.y * 128;
    const int blockN = blockIdx.x * 128;

    float acc[2][8][4];
    #pragma unroll
    for (int i = 0; i < 2; i++)
        #pragma unroll
        for (int j = 0; j < 8; j++)
            #pragma unroll
            for (int q = 0; q < 4; q++) acc[i][j][q] = 0.f;

    for (int k0 = 0; k0 < K; k0 += 32) {
        // ---- fill A tile: 128 rows x 32 cols (1024 float4 / 256 thr = 4 ea)
        #pragma unroll
        for (int it = 0; it < 4; it++) {
            const int idx = tid + it * 256;
            const int row = idx >> 3;
            const int c4  = (idx & 7) << 2;
            float4 v = *(const float4*)(A + (size_t)(blockM + row) * K + k0 + c4);
            uint16_t h0,h1,h2,h3,l0,l1,l2,l3;
            split2(v.x,h0,l0); split2(v.y,h1,l1);
            split2(v.z,h2,l2); split2(v.w,h3,l3);
            uint2 uh, ul;
            uh.x = (uint32_t)h0 | ((uint32_t)h1 << 16);
            uh.y = (uint32_t)h2 | ((uint32_t)h3 << 16);
            ul.x = (uint32_t)l0 | ((uint32_t)l1 << 16);
            ul.y = (uint32_t)l2 | ((uint32_t)l3 << 16);
            *(uint2*)&As_hi[row][c4] = uh;
            *(uint2*)&As_lo[row][c4] = ul;
        }
        // ---- fill B tile: 32 rows x 128 cols
        #pragma unroll
        for (int it = 0; it < 4; it++) {
            const int idx = tid + it * 256;
            const int row = idx >> 5;
            const int c4  = (idx & 31) << 2;
            float4 v = *(const float4*)(B + (size_t)(k0 + row) * N + blockN + c4);
            uint16_t h0,h1,h2,h3,l0,l1,l2,l3;
            split2(v.x,h0,l0); split2(v.y,h1,l1);
            split2(v.z,h2,l2); split2(v.w,h3,l3);
            uint2 uh, ul;
            uh.x = (uint32_t)h0 | ((uint32_t)h1 << 16);
            uh.y = (uint32_t)h2 | ((uint32_t)h3 << 16);
            ul.x = (uint32_t)l0 | ((uint32_t)l1 << 16);
            ul.y = (uint32_t)l2 | ((uint32_t)l3 << 16);
            *(uint2*)&Bs_hi[row][c4] = uh;
            *(uint2*)&Bs_lo[row][c4] = ul;
        }
        __syncthreads();

        #pragma unroll
        for (int ks = 0; ks < 2; ks++) {
            const int kk = ks * 16;
            // A fragments (hi and lo) for 2 m16 tiles
            uint32_t ah[2][4], al[2][4];
            #pragma unroll
            for (int mf = 0; mf < 2; mf++) {
                const int row = m_base + mf * 16 + (lane & 15);
                const int col = kk + ((lane >> 4) << 3);
                ldsm_x4(ah[mf], sm_u32(&As_hi[row][col]));
                ldsm_x4(al[mf], sm_u32(&As_lo[row][col]));
            }
            #pragma unroll
            for (int ng = 0; ng < 4; ng++) {
                const int brow = kk + (lane & 15);
                const int bcol = n_base + ng * 16 + ((lane >> 4) << 3);
                uint32_t bh[4], bl[4];
                ldsm_x4_t(bh, sm_u32(&Bs_hi[brow][bcol]));
                ldsm_x4_t(bl, sm_u32(&Bs_lo[brow][bcol]));
                #pragma unroll
                for (int mf = 0; mf < 2; mf++) {
                    mma16816(acc[mf][ng*2+0], ah[mf], bh + 0);
                    mma16816(acc[mf][ng*2+0], ah[mf], bl + 0);
                    mma16816(acc[mf][ng*2+0], al[mf], bh + 0);
                    mma16816(acc[mf][ng*2+1], ah[mf], bh + 2);
                    mma16816(acc[mf][ng*2+1], ah[mf], bl + 2);
                    mma16816(acc[mf][ng*2+1], al[mf], bh + 2);
                }
            }
        }
        __syncthreads();
    }

    // ---- epilogue
    #pragma unroll
    for (int mf = 0; mf < 2; mf++) {
        const int r0 = blockM + m_base + mf * 16 + (lane >> 2);
        #pragma unroll
        for (int nf = 0; nf < 8; nf++) {
            const int cN = blockN + n_base + nf * 8 + (lane & 3) * 2;
            float2 v0 = make_float2(acc[mf][nf][0], acc[mf][nf][1]);
            float2 v1 = make_float2(acc[mf][nf][2], acc[mf][nf][3]);
            if (BIAS) {
                const float b0 = bias[cN], b1 = bias[cN + 1];
                v0.x += b0; v0.y += b1; v1.x += b0; v1.y += b1;
            }
            *(float2*)(C + (size_t)r0 * N + cN) = v0;
            *(float2*)(C + (size_t)(r0 + 8) * N + cN) = v1;
        }
    }
}

// ---------------------------------------------------------------------------
// Spatial attention: one block per (n*t, head). 256 threads, 1 query each.
// ---------------------------------------------------------------------------
__global__ __launch_bounds__(256) void spatial_attn(
    const float* __restrict__ qkv, float* __restrict__ out)
{
    extern __shared__ float sm[];
    float* Ks = sm;             // [256][64]
    float* Vs = sm + 256 * 64;  // [256][64]

    const int inst = blockIdx.x;     // 0..255
    const int h = inst & 7;
    const int nt = inst >> 3;        // 0..31
    const int tid = threadIdx.x;     // query index s

    const float* base = qkv + (size_t)nt * SB * THREE_D;

    for (int i = tid; i < 256 * 16; i += 256) {
        const int row = i >> 4;
        const int c4 = (i & 15) << 2;
        const float* rb = base + (size_t)row * THREE_D + h * DH;
        *(float4*)(Ks + row * DH + c4) = *(const float4*)(rb + 1024 + c4);
        *(float4*)(Vs + row * DH + c4) = *(const float4*)(rb + 2048 + c4);
    }

    float q[DH];
    {
        const float* qp = base + (size_t)tid * THREE_D + h * DH;
        #pragma unroll
        for (int d4 = 0; d4 < 16; d4++) {
            float4 t = *(const float4*)(qp + d4 * 4);
            q[d4*4+0] = t.x; q[d4*4+1] = t.y; q[d4*4+2] = t.z; q[d4*4+3] = t.w;
        }
    }
    __syncthreads();

    const float scale = 0.125f;
    float m = -INFINITY, l = 0.f;
    float acc[DH];
    #pragma unroll
    for (int d = 0; d < DH; d++) acc[d] = 0.f;

    for (int j = 0; j < SB; j++) {
        const float* kj = Ks + j * DH;
        float s = 0.f;
        #pragma unroll
        for (int d = 0; d < DH; d++) s = fmaf(q[d], kj[d], s);
        s *= scale;
        const float mn = fmaxf(m, s);
        const float c = __expf(m - mn);
        const float p = __expf(s - mn);
        l = l * c + p;
        m = mn;
        const float* vj = Vs + j * DH;
        #pragma unroll
        for (int d = 0; d < DH; d++) acc[d] = fmaf(acc[d], c, p * vj[d]);
    }

    const float inv = 1.f / l;
    float* op = out + ((size_t)nt * SB + tid) * DB + h * DH;
    #pragma unroll
    for (int d4 = 0; d4 < 16; d4++) {
        float4 o;
        o.x = acc[d4*4+0]*inv; o.y = acc[d4*4+1]*inv;
        o.z = acc[d4*4+2]*inv; o.w = acc[d4*4+3]*inv;
        *(float4*)(op + d4 * 4) = o;
    }
}

// ---------------------------------------------------------------------------
// Temporal attention: one block per (n, s). 128 threads: tid = t*8 + h.
// ---------------------------------------------------------------------------
__global__ __launch_bounds__(128) void temporal_attn(
    const float* __restrict__ qkv, float* __restrict__ out)
{
    extern __shared__ float sm[];
    float* Ks = sm;              // [16][512]
    float* Vs = sm + 16 * 512;   // [16][512]

    const int ns = blockIdx.x;
    const int n = ns >> 8;
    const int s = ns & 255;
    const int tid = threadIdx.x;
    const int h = tid & 7;
    const int t = tid >> 3;

    const size_t tstride = (size_t)SB * THREE_D;
    const float* rowbase = qkv + ((size_t)(n * TB) * SB + s) * THREE_D;

    for (int i = tid; i < 16 * 128; i += 128) {
        const int row = i >> 7;
        const int c4 = (i & 127) << 2;
        const float* rb = rowbase + row * tstride;
        *(float4*)(Ks + row * 512 + c4) = *(const float4*)(rb + 1536 + c4);
        *(float4*)(Vs + row * 512 + c4) = *(const float4*)(rb + 2560 + c4);
    }

    float q[DH];
    {
        const float* qp = rowbase + t * tstride + 512 + h * DH;
        #pragma unroll
        for (int d4 = 0; d4 < 16; d4++) {
            float4 v = *(const float4*)(qp + d4 * 4);
            q[d4*4+0] = v.x; q[d4*4+1] = v.y; q[d4*4+2] = v.z; q[d4*4+3] = v.w;
        }
    }
    __syncthreads();

    const float scale = 0.125f;
    float sc[TB];
    float mmax = -INFINITY;
    #pragma unroll
    for (int j = 0; j < TB; j++) {
        const float* kj = Ks + j * 512 + h * DH;
        float d0 = 0.f;
        #pragma unroll
        for (int d = 0; d < DH; d++) d0 = fmaf(q[d], kj[d], d0);
        sc[j] = d0 * scale;
        mmax = fmaxf(mmax, sc[j]);
    }
    float lsum = 0.f;
    #pragma unroll
    for (int j = 0; j < TB; j++) {
        sc[j] = __expf(sc[j] - mmax);
        lsum += sc[j];
    }
    const float inv = 1.f / lsum;

    float acc[DH];
    #pragma unroll
    for (int d = 0; d < DH; d++) acc[d] = 0.f;
    #pragma unroll
    for (int j = 0; j < TB; j++) {
        const float p = sc[j];
        const float* vj = Vs + j * 512 + h * DH;
        #pragma unroll
        for (int d = 0; d < DH; d++) acc[d] = fmaf(p, vj[d], acc[d]);
    }

    float* op = out + ((size_t)(n * TB + t) * SB + s) * DB + 512 + h * DH;
    #pragma unroll
    for (int d4 = 0; d4 < 16; d4++) {
        float4 o;
        o.x = acc[d4*4+0]*inv; o.y = acc[d4*4+1]*inv;
        o.z = acc[d4*4+2]*inv; o.w = acc[d4*4+3]*inv;
        *(float4*)(op + d4 * 4) = o;
    }
}

// ---------------------------------------------------------------------------
extern "C" void kernel_launch(void* const* d_in, const int* in_sizes, int n_in,
                              void* d_out, int out_size)
{
    const float* x     = (const float*)d_in[0];  // [2,16,256,1024]
    const float* Wqkv  = (const float*)d_in[1];  // [1024,3072]
    const float* Wproj = (const float*)d_in[2];  // [1024,1024]
    const float* bproj = (const float*)d_in[3];  // [1024]
    float* out = (float*)d_out;

    float* qkv_ptr = nullptr;
    float* attn_ptr = nullptr;
    cudaGetSymbolAddress((void**)&qkv_ptr, g_qkv);
    cudaGetSymbolAddress((void**)&attn_ptr, g_attn);

    cudaFuncSetAttribute(spatial_attn,
        cudaFuncAttributeMaxDynamicSharedMemorySize, 2 * 256 * DH * 4);
    cudaFuncSetAttribute(temporal_attn,
        cudaFuncAttributeMaxDynamicSharedMemorySize, 2 * 16 * 512 * 4);

    // 1) qkv = x @ Wqkv : [8192,1024] x [1024,3072]
    {
        dim3 grid(THREE_D / 128, ROWS / 128);
        gemm_bf16x3<false><<<grid, 256>>>(x, Wqkv, nullptr, qkv_ptr,
                                          ROWS, THREE_D, DB);
    }

    // 2) spatial attention: 256 instances (n*t, head)
    spatial_attn<<<NB * TB * HEADS, 256, 2 * 256 * DH * 4>>>(qkv_ptr, attn_ptr);

    // 3) temporal attention: 512 blocks (n, s)
    temporal_attn<<<NB * SB, 128, 2 * 16 * 512 * 4>>>(qkv_ptr, attn_ptr);

    // 4) out = attn @ Wproj + bproj : [8192,1024] x [1024,1024]
    {
        dim3 grid(DB / 128, ROWS / 128);
        gemm_bf16x3<true><<<grid, 256>>>(attn_ptr, Wproj, bproj, out,
                                         ROWS, DB, DB);
    }
}

// round 8
// speedup vs baseline: 2.0859x; 1.2636x over previous
#include <cuda_runtime.h>
#include <cuda_bf16.h>
#include <math.h>
#include <stdint.h>

// Problem: x[N=2,T=16,S=256,D=1024]
// qkv = x @ Wqkv[1024,3072]; heads=8, Dh=64, scale=0.125
// spatial attn over S per (n,t,h); temporal attn over T per (n,s,h)
// out = concat(x_s, x_t) @ Wproj + bproj

#define NB 2
#define TB 16
#define SB 256
#define DB 1024
#define ROWS (NB*TB*SB)      // 8192
#define THREE_D (3*DB)       // 3072
#define HEADS 8
#define DH 64

// Scratch (device globals; allocation-free per harness rules)
__device__ float g_qkv[(size_t)ROWS * THREE_D];          // fp32 qkv, ~100.7MB
__device__ __nv_bfloat16 g_xh[(size_t)ROWS * DB];        // x hi/lo
__device__ __nv_bfloat16 g_xl[(size_t)ROWS * DB];
__device__ __nv_bfloat16 g_wqh[(size_t)DB * THREE_D];    // Wqkv hi/lo
__device__ __nv_bfloat16 g_wql[(size_t)DB * THREE_D];
__device__ __nv_bfloat16 g_wph[(size_t)DB * DB];         // Wproj hi/lo
__device__ __nv_bfloat16 g_wpl[(size_t)DB * DB];
__device__ __nv_bfloat16 g_ah[(size_t)ROWS * DB];        // attn out hi/lo
__device__ __nv_bfloat16 g_al[(size_t)ROWS * DB];

// ---------------------------------------------------------------------------
// helpers
// ---------------------------------------------------------------------------
__device__ __forceinline__ uint32_t sm_u32(const void* p) {
    return (uint32_t)__cvta_generic_to_shared(p);
}
__device__ __forceinline__ void cp16(void* sdst, const void* gsrc) {
    asm volatile("cp.async.cg.shared.global [%0], [%1], 16;\n"
                 :: "r"(sm_u32(sdst)), "l"(gsrc));
}
__device__ __forceinline__ void cp_commit() {
    asm volatile("cp.async.commit_group;\n");
}
template<int NPEND>
__device__ __forceinline__ void cp_wait() {
    asm volatile("cp.async.wait_group %0;\n" :: "n"(NPEND));
}
__device__ __forceinline__ void ldsm_x4(uint32_t* r, uint32_t addr) {
    asm volatile("ldmatrix.sync.aligned.m8n8.x4.shared.b16 {%0,%1,%2,%3}, [%4];"
                 : "=r"(r[0]), "=r"(r[1]), "=r"(r[2]), "=r"(r[3]) : "r"(addr));
}
__device__ __forceinline__ void ldsm_x4_t(uint32_t* r, uint32_t addr) {
    asm volatile("ldmatrix.sync.aligned.m8n8.x4.trans.shared.b16 {%0,%1,%2,%3}, [%4];"
                 : "=r"(r[0]), "=r"(r[1]), "=r"(r[2]), "=r"(r[3]) : "r"(addr));
}
__device__ __forceinline__ void mma16816(float* c, const uint32_t* a,
                                         const uint32_t* b) {
    asm volatile(
        "mma.sync.aligned.m16n8k16.row.col.f32.bf16.bf16.f32 "
        "{%0,%1,%2,%3}, {%4,%5,%6,%7}, {%8,%9}, {%0,%1,%2,%3};"
        : "+f"(c[0]), "+f"(c[1]), "+f"(c[2]), "+f"(c[3])
        : "r"(a[0]), "r"(a[1]), "r"(a[2]), "r"(a[3]), "r"(b[0]), "r"(b[1]));
}
__device__ __forceinline__ void split2(float v, uint16_t& hi, uint16_t& lo) {
    __nv_bfloat16 h = __float2bfloat16(v);
    __nv_bfloat16 l = __float2bfloat16(v - __bfloat162float(h));
    hi = __bfloat16_as_ushort(h);
    lo = __bfloat16_as_ushort(l);
}

// ---------------------------------------------------------------------------
// Elementwise fp32 -> (bf16 hi, bf16 lo) split, float4-vectorized.
// ---------------------------------------------------------------------------
__global__ __launch_bounds__(256) void split_kernel(
    const float* __restrict__ in, __nv_bfloat16* __restrict__ hi,
    __nv_bfloat16* __restrict__ lo, int n4)
{
    const int i = blockIdx.x * 256 + threadIdx.x;
    if (i >= n4) return;
    float4 v = ((const float4*)in)[i];
    uint16_t h0,h1,h2,h3,l0,l1,l2,l3;
    split2(v.x,h0,l0); split2(v.y,h1,l1);
    split2(v.z,h2,l2); split2(v.w,h3,l3);
    uint2 uh, ul;
    uh.x = (uint32_t)h0 | ((uint32_t)h1 << 16);
    uh.y = (uint32_t)h2 | ((uint32_t)h3 << 16);
    ul.x = (uint32_t)l0 | ((uint32_t)l1 << 16);
    ul.y = (uint32_t)l2 | ((uint32_t)l3 << 16);
    ((uint2*)hi)[i] = uh;
    ((uint2*)lo)[i] = ul;
}

// ---------------------------------------------------------------------------
// Tensor-core GEMM, pre-split bf16 inputs, cp.async double-buffered.
// C = Ah@Bh + Ah@Bl + Al@Bh (+bias), fp32 accum/out.
// BM=BN=128, BK=32, 256 thr = 8 warps (4m x 2n), warp tile 32m x 64n.
// ---------------------------------------------------------------------------
#define APAD 40     // A row stride (elements): 80B, 16B-aligned, ldsm conflict-free
#define BPAD 136    // B row stride: 272B
#define A_ELS (128 * APAD)
#define B_ELS (32 * BPAD)
#define STAGE_ELS (2 * A_ELS + 2 * B_ELS)
#define GEMM_SMEM (2 * STAGE_ELS * 2)   // bytes, 2 stages

template<bool BIAS>
__global__ __launch_bounds__(256, 1) void gemm_pre(
    const __nv_bfloat16* __restrict__ Ah, const __nv_bfloat16* __restrict__ Al,
    const __nv_bfloat16* __restrict__ Bh, const __nv_bfloat16* __restrict__ Bl,
    const float* __restrict__ bias, float* __restrict__ C,
    int M, int N, int K)
{
    extern __shared__ __nv_bfloat16 smem[];

    const int tid  = threadIdx.x;
    const int lane = tid & 31;
    const int warp = tid >> 5;
    const int m_base = (warp & 3) * 32;
    const int n_base = (warp >> 2) * 64;
    const int blockM = blockIdx.y * 128;
    const int blockN = blockIdx.x * 128;

    // per-thread load coords (2 chunks of 16B per array per thread)
    // A: 128 rows x 32 cols = 512 x 16B chunks (4/row)
    // B: 32 rows x 128 cols = 512 x 16B chunks (16/row)
    const int aRow0 = tid >> 2, aC0 = (tid & 3) << 3;
    const int aRow1 = (tid + 256) >> 2, aC1 = ((tid + 256) & 3) << 3;
    const int bRow0 = tid >> 4, bC0 = (tid & 15) << 3;
    const int bRow1 = (tid + 256) >> 4, bC1 = ((tid + 256) & 15) << 3;

    float acc[2][8][4];
    #pragma unroll
    for (int i = 0; i < 2; i++)
        #pragma unroll
        for (int j = 0; j < 8; j++)
            #pragma unroll
            for (int q = 0; q < 4; q++) acc[i][j][q] = 0.f;

    auto load_tile = [&](int stage, int k0) {
        __nv_bfloat16* sAh = smem + stage * STAGE_ELS;
        __nv_bfloat16* sAl = sAh + A_ELS;
        __nv_bfloat16* sBh = sAl + A_ELS;
        __nv_bfloat16* sBl = sBh + B_ELS;
        cp16(sAh + aRow0 * APAD + aC0, Ah + (size_t)(blockM + aRow0) * K + k0 + aC0);
        cp16(sAh + aRow1 * APAD + aC1, Ah + (size_t)(blockM + aRow1) * K + k0 + aC1);
        cp16(sAl + aRow0 * APAD + aC0, Al + (size_t)(blockM + aRow0) * K + k0 + aC0);
        cp16(sAl + aRow1 * APAD + aC1, Al + (size_t)(blockM + aRow1) * K + k0 + aC1);
        cp16(sBh + bRow0 * BPAD + bC0, Bh + (size_t)(k0 + bRow0) * N + blockN + bC0);
        cp16(sBh + bRow1 * BPAD + bC1, Bh + (size_t)(k0 + bRow1) * N + blockN + bC1);
        cp16(sBl + bRow0 * BPAD + bC0, Bl + (size_t)(k0 + bRow0) * N + blockN + bC0);
        cp16(sBl + bRow1 * BPAD + bC1, Bl + (size_t)(k0 + bRow1) * N + blockN + bC1);
    };

    const int NT = K >> 5;   // K/32
    load_tile(0, 0);
    cp_commit();

    for (int kt = 0; kt < NT; kt++) {
        if (kt + 1 < NT) {
            load_tile((kt + 1) & 1, (kt + 1) << 5);
            cp_commit();
            cp_wait<1>();
        } else {
            cp_wait<0>();
        }
        __syncthreads();

        const __nv_bfloat16* sAh = smem + (kt & 1) * STAGE_ELS;
        const __nv_bfloat16* sAl = sAh + A_ELS;
        const __nv_bfloat16* sBh = sAl + A_ELS;
        const __nv_bfloat16* sBl = sBh + B_ELS;

        #pragma unroll
        for (int ks = 0; ks < 2; ks++) {
            const int kk = ks * 16;
            uint32_t ah[2][4], al[2][4];
            #pragma unroll
            for (int mf = 0; mf < 2; mf++) {
                const int row = m_base + mf * 16 + (lane & 15);
                const int col = kk + ((lane >> 4) << 3);
                ldsm_x4(ah[mf], sm_u32(sAh + row * APAD + col));
                ldsm_x4(al[mf], sm_u32(sAl + row * APAD + col));
            }
            #pragma unroll
            for (int ng = 0; ng < 4; ng++) {
                const int brow = kk + (lane & 15);
                const int bcol = n_base + ng * 16 + ((lane >> 4) << 3);
                uint32_t bh[4], bl[4];
                ldsm_x4_t(bh, sm_u32(sBh + brow * BPAD + bcol));
                ldsm_x4_t(bl, sm_u32(sBl + brow * BPAD + bcol));
                #pragma unroll
                for (int mf = 0; mf < 2; mf++) {
                    mma16816(acc[mf][ng*2+0], ah[mf], bh + 0);
                    mma16816(acc[mf][ng*2+0], ah[mf], bl + 0);
                    mma16816(acc[mf][ng*2+0], al[mf], bh + 0);
                    mma16816(acc[mf][ng*2+1], ah[mf], bh + 2);
                    mma16816(acc[mf][ng*2+1], ah[mf], bl + 2);
                    mma16816(acc[mf][ng*2+1], al[mf], bh + 2);
                }
            }
        }
        __syncthreads();
    }

    #pragma unroll
    for (int mf = 0; mf < 2; mf++) {
        const int r0 = blockM + m_base + mf * 16 + (lane >> 2);
        #pragma unroll
        for (int nf = 0; nf < 8; nf++) {
            const int cN = blockN + n_base + nf * 8 + (lane & 3) * 2;
            float2 v0 = make_float2(acc[mf][nf][0], acc[mf][nf][1]);
            float2 v1 = make_float2(acc[mf][nf][2], acc[mf][nf][3]);
            if (BIAS) {
                const float b0 = bias[cN], b1 = bias[cN + 1];
                v0.x += b0; v0.y += b1; v1.x += b0; v1.y += b1;
            }
            *(float2*)(C + (size_t)r0 * N + cN) = v0;
            *(float2*)(C + (size_t)(r0 + 8) * N + cN) = v1;
        }
    }
}

// ---------------------------------------------------------------------------
// Spatial attention: one block per (n*t, head). 256 threads, 1 query each.
// Outputs bf16 hi/lo split (feeds GEMM2 directly).
// ---------------------------------------------------------------------------
__global__ __launch_bounds__(256) void spatial_attn(
    const float* __restrict__ qkv,
    __nv_bfloat16* __restrict__ oh, __nv_bfloat16* __restrict__ ol)
{
    extern __shared__ float sm[];
    float* Ks = sm;             // [256][64]
    float* Vs = sm + 256 * 64;  // [256][64]

    const int inst = blockIdx.x;     // 0..255
    const int h = inst & 7;
    const int nt = inst >> 3;        // 0..31
    const int tid = threadIdx.x;     // query index s

    const float* base = qkv + (size_t)nt * SB * THREE_D;

    for (int i = tid; i < 256 * 16; i += 256) {
        const int row = i >> 4;
        const int c4 = (i & 15) << 2;
        const float* rb = base + (size_t)row * THREE_D + h * DH;
        *(float4*)(Ks + row * DH + c4) = *(const float4*)(rb + 1024 + c4);
        *(float4*)(Vs + row * DH + c4) = *(const float4*)(rb + 2048 + c4);
    }

    float q[DH];
    {
        const float* qp = base + (size_t)tid * THREE_D + h * DH;
        #pragma unroll
        for (int d4 = 0; d4 < 16; d4++) {
            float4 t = *(const float4*)(qp + d4 * 4);
            q[d4*4+0] = t.x; q[d4*4+1] = t.y; q[d4*4+2] = t.z; q[d4*4+3] = t.w;
        }
    }
    __syncthreads();

    const float scale = 0.125f;
    float m = -INFINITY, l = 0.f;
    float acc[DH];
    #pragma unroll
    for (int d = 0; d < DH; d++) acc[d] = 0.f;

    for (int j = 0; j < SB; j++) {
        const float* kj = Ks + j * DH;
        float s = 0.f;
        #pragma unroll
        for (int d = 0; d < DH; d++) s = fmaf(q[d], kj[d], s);
        s *= scale;
        const float mn = fmaxf(m, s);
        const float c = __expf(m - mn);
        const float p = __expf(s - mn);
        l = l * c + p;
        m = mn;
        const float* vj = Vs + j * DH;
        #pragma unroll
        for (int d = 0; d < DH; d++) acc[d] = fmaf(acc[d], c, p * vj[d]);
    }

    const float inv = 1.f / l;
    const size_t obase = ((size_t)nt * SB + tid) * DB + h * DH;   // cols [0,512)
    #pragma unroll
    for (int d8 = 0; d8 < 8; d8++) {
        uint4 uh, ul;
        uint16_t hh[8], lt[8];
        #pragma unroll
        for (int e = 0; e < 8; e++)
            split2(acc[d8 * 8 + e] * inv, hh[e], lt[e]);
        uh.x = (uint32_t)hh[0] | ((uint32_t)hh[1] << 16);
        uh.y = (uint32_t)hh[2] | ((uint32_t)hh[3] << 16);
        uh.z = (uint32_t)hh[4] | ((uint32_t)hh[5] << 16);
        uh.w = (uint32_t)hh[6] | ((uint32_t)hh[7] << 16);
        ul.x = (uint32_t)lt[0] | ((uint32_t)lt[1] << 16);
        ul.y = (uint32_t)lt[2] | ((uint32_t)lt[3] << 16);
        ul.z = (uint32_t)lt[4] | ((uint32_t)lt[5] << 16);
        ul.w = (uint32_t)lt[6] | ((uint32_t)lt[7] << 16);
        *(uint4*)(oh + obase + d8 * 8) = uh;
        *(uint4*)(ol + obase + d8 * 8) = ul;
    }
}

// ---------------------------------------------------------------------------
// Temporal attention: one block per (n, s). 128 threads: tid = t*8 + h.
// Outputs bf16 hi/lo split.
// ---------------------------------------------------------------------------
__global__ __launch_bounds__(128) void temporal_attn(
    const float* __restrict__ qkv,
    __nv_bfloat16* __restrict__ oh, __nv_bfloat16* __restrict__ ol)
{
    extern __shared__ float sm[];
    float* Ks = sm;              // [16][512]
    float* Vs = sm + 16 * 512;   // [16][512]

    const int ns = blockIdx.x;
    const int n = ns >> 8;
    const int s = ns & 255;
    const int tid = threadIdx.x;
    const int h = tid & 7;
    const int t = tid >> 3;

    const size_t tstride = (size_t)SB * THREE_D;
    const float* rowbase = qkv + ((size_t)(n * TB) * SB + s) * THREE_D;

    for (int i = tid; i < 16 * 128; i += 128) {
        const int row = i >> 7;
        const int c4 = (i & 127) << 2;
        const float* rb = rowbase + row * tstride;
        *(float4*)(Ks + row * 512 + c4) = *(const float4*)(rb + 1536 + c4);
        *(float4*)(Vs + row * 512 + c4) = *(const float4*)(rb + 2560 + c4);
    }

    float q[DH];
    {
        const float* qp = rowbase + t * tstride + 512 + h * DH;
        #pragma unroll
        for (int d4 = 0; d4 < 16; d4++) {
            float4 v = *(const float4*)(qp + d4 * 4);
            q[d4*4+0] = v.x; q[d4*4+1] = v.y; q[d4*4+2] = v.z; q[d4*4+3] = v.w;
        }
    }
    __syncthreads();

    const float scale = 0.125f;
    float sc[TB];
    float mmax = -INFINITY;
    #pragma unroll
    for (int j = 0; j < TB; j++) {
        const float* kj = Ks + j * 512 + h * DH;
        float d0 = 0.f;
        #pragma unroll
        for (int d = 0; d < DH; d++) d0 = fmaf(q[d], kj[d], d0);
        sc[j] = d0 * scale;
        mmax = fmaxf(mmax, sc[j]);
    }
    float lsum = 0.f;
    #pragma unroll
    for (int j = 0; j < TB; j++) {
        sc[j] = __expf(sc[j] - mmax);
        lsum += sc[j];
    }
    const float inv = 1.f / lsum;

    float acc[DH];
    #pragma unroll
    for (int d = 0; d < DH; d++) acc[d] = 0.f;
    #pragma unroll
    for (int j = 0; j < TB; j++) {
        const float p = sc[j];
        const float* vj = Vs + j * 512 + h * DH;
        #pragma unroll
        for (int d = 0; d < DH; d++) acc[d] = fmaf(p, vj[d], acc[d]);
    }

    const size_t obase = ((size_t)(n * TB + t) * SB + s) * DB + 512 + h * DH;
    #pragma unroll
    for (int d8 = 0; d8 < 8; d8++) {
        uint4 uh, ul;
        uint16_t hh[8], lt[8];
        #pragma unroll
        for (int e = 0; e < 8; e++)
            split2(acc[d8 * 8 + e] * inv, hh[e], lt[e]);
        uh.x = (uint32_t)hh[0] | ((uint32_t)hh[1] << 16);
        uh.y = (uint32_t)hh[2] | ((uint32_t)hh[3] << 16);
        uh.z = (uint32_t)hh[4] | ((uint32_t)hh[5] << 16);
        uh.w = (uint32_t)hh[6] | ((uint32_t)hh[7] << 16);
        ul.x = (uint32_t)lt[0] | ((uint32_t)lt[1] << 16);
        ul.y = (uint32_t)lt[2] | ((uint32_t)lt[3] << 16);
        ul.z = (uint32_t)lt[4] | ((uint32_t)lt[5] << 16);
        ul.w = (uint32_t)lt[6] | ((uint32_t)lt[7] << 16);
        *(uint4*)(oh + obase + d8 * 8) = uh;
        *(uint4*)(ol + obase + d8 * 8) = ul;
    }
}

// ---------------------------------------------------------------------------
extern "C" void kernel_launch(void* const* d_in, const int* in_sizes, int n_in,
                              void* d_out, int out_size)
{
    const float* x     = (const float*)d_in[0];  // [2,16,256,1024]
    const float* Wqkv  = (const float*)d_in[1];  // [1024,3072]
    const float* Wproj = (const float*)d_in[2];  // [1024,1024]
    const float* bproj = (const float*)d_in[3];  // [1024]
    float* out = (float*)d_out;

    float *qkv_ptr;
    __nv_bfloat16 *xh, *xl, *wqh, *wql, *wph, *wpl, *ah, *al;
    cudaGetSymbolAddress((void**)&qkv_ptr, g_qkv);
    cudaGetSymbolAddress((void**)&xh, g_xh);
    cudaGetSymbolAddress((void**)&xl, g_xl);
    cudaGetSymbolAddress((void**)&wqh, g_wqh);
    cudaGetSymbolAddress((void**)&wql, g_wql);
    cudaGetSymbolAddress((void**)&wph, g_wph);
    cudaGetSymbolAddress((void**)&wpl, g_wpl);
    cudaGetSymbolAddress((void**)&ah, g_ah);
    cudaGetSymbolAddress((void**)&al, g_al);

    cudaFuncSetAttribute(gemm_pre<false>,
        cudaFuncAttributeMaxDynamicSharedMemorySize, GEMM_SMEM);
    cudaFuncSetAttribute(gemm_pre<true>,
        cudaFuncAttributeMaxDynamicSharedMemorySize, GEMM_SMEM);
    cudaFuncSetAttribute(spatial_attn,
        cudaFuncAttributeMaxDynamicSharedMemorySize, 2 * 256 * DH * 4);
    cudaFuncSetAttribute(temporal_attn,
        cudaFuncAttributeMaxDynamicSharedMemorySize, 2 * 16 * 512 * 4);

    // 0) pre-split inputs to bf16 hi/lo
    {
        int n4x = ROWS * DB / 4;        // 2,097,152
        split_kernel<<<n4x / 256, 256>>>(x, xh, xl, n4x);
        int n4q = DB * THREE_D / 4;     // 786,432
        split_kernel<<<n4q / 256, 256>>>(Wqkv, wqh, wql, n4q);
        int n4p = DB * DB / 4;          // 262,144
        split_kernel<<<n4p / 256, 256>>>(Wproj, wph, wpl, n4p);
    }

    // 1) qkv = x @ Wqkv : [8192,1024] x [1024,3072]
    {
        dim3 grid(THREE_D / 128, ROWS / 128);
        gemm_pre<false><<<grid, 256, GEMM_SMEM>>>(xh, xl, wqh, wql, nullptr,
                                                  qkv_ptr, ROWS, THREE_D, DB);
    }

    // 2) spatial attention: 256 instances (n*t, head) -> bf16 hi/lo
    spatial_attn<<<NB * TB * HEADS, 256, 2 * 256 * DH * 4>>>(qkv_ptr, ah, al);

    // 3) temporal attention: 512 blocks (n, s) -> bf16 hi/lo
    temporal_attn<<<NB * SB, 128, 2 * 16 * 512 * 4>>>(qkv_ptr, ah, al);

    // 4) out = attn @ Wproj + bproj : [8192,1024] x [1024,1024]
    {
        dim3 grid(DB / 128, ROWS / 128);
        gemm_pre<true><<<grid, 256, GEMM_SMEM>>>(ah, al, wph, wpl, bproj,
                                                 out, ROWS, DB, DB);
    }
}

// round 9
// speedup vs baseline: 2.3839x; 1.1428x over previous
#include <cuda_runtime.h>
#include <cuda_bf16.h>
#include <math.h>
#include <stdint.h>

// Problem: x[N=2,T=16,S=256,D=1024]
// qkv = x @ Wqkv[1024,3072]; heads=8, Dh=64, scale=0.125
// spatial attn over S per (n,t,h); temporal attn over T per (n,s,h)
// out = concat(x_s, x_t) @ Wproj + bproj

#define NB 2
#define TB 16
#define SB 256
#define DB 1024
#define ROWS (NB*TB*SB)      // 8192
#define THREE_D (3*DB)       // 3072
#define HEADS 8
#define DH 64

// Scratch (device globals; allocation-free per harness rules)
__device__ float g_qkv[(size_t)ROWS * THREE_D];          // fp32 qkv, ~100.7MB
__device__ __nv_bfloat16 g_xh[(size_t)ROWS * DB];        // x hi/lo
__device__ __nv_bfloat16 g_xl[(size_t)ROWS * DB];
__device__ __nv_bfloat16 g_wqh[(size_t)DB * THREE_D];    // Wqkv hi/lo
__device__ __nv_bfloat16 g_wql[(size_t)DB * THREE_D];
__device__ __nv_bfloat16 g_wph[(size_t)DB * DB];         // Wproj hi/lo
__device__ __nv_bfloat16 g_wpl[(size_t)DB * DB];
__device__ __nv_bfloat16 g_ah[(size_t)ROWS * DB];        // attn out hi/lo
__device__ __nv_bfloat16 g_al[(size_t)ROWS * DB];

// ---------------------------------------------------------------------------
// helpers
// ---------------------------------------------------------------------------
__device__ __forceinline__ uint32_t sm_u32(const void* p) {
    return (uint32_t)__cvta_generic_to_shared(p);
}
__device__ __forceinline__ void cp16(void* sdst, const void* gsrc) {
    asm volatile("cp.async.cg.shared.global [%0], [%1], 16;\n"
                 :: "r"(sm_u32(sdst)), "l"(gsrc));
}
__device__ __forceinline__ void cp_commit() {
    asm volatile("cp.async.commit_group;\n");
}
template<int NPEND>
__device__ __forceinline__ void cp_wait() {
    asm volatile("cp.async.wait_group %0;\n" :: "n"(NPEND));
}
__device__ __forceinline__ void ldsm_x4(uint32_t* r, uint32_t addr) {
    asm volatile("ldmatrix.sync.aligned.m8n8.x4.shared.b16 {%0,%1,%2,%3}, [%4];"
                 : "=r"(r[0]), "=r"(r[1]), "=r"(r[2]), "=r"(r[3]) : "r"(addr));
}
__device__ __forceinline__ void ldsm_x4_t(uint32_t* r, uint32_t addr) {
    asm volatile("ldmatrix.sync.aligned.m8n8.x4.trans.shared.b16 {%0,%1,%2,%3}, [%4];"
                 : "=r"(r[0]), "=r"(r[1]), "=r"(r[2]), "=r"(r[3]) : "r"(addr));
}
__device__ __forceinline__ void mma16816(float* c, const uint32_t* a,
                                         const uint32_t* b) {
    asm volatile(
        "mma.sync.aligned.m16n8k16.row.col.f32.bf16.bf16.f32 "
        "{%0,%1,%2,%3}, {%4,%5,%6,%7}, {%8,%9}, {%0,%1,%2,%3};"
        : "+f"(c[0]), "+f"(c[1]), "+f"(c[2]), "+f"(c[3])
        : "r"(a[0]), "r"(a[1]), "r"(a[2]), "r"(a[3]), "r"(b[0]), "r"(b[1]));
}
__device__ __forceinline__ void split2(float v, uint16_t& hi, uint16_t& lo) {
    __nv_bfloat16 h = __float2bfloat16(v);
    __nv_bfloat16 l = __float2bfloat16(v - __bfloat162float(h));
    hi = __bfloat16_as_ushort(h);
    lo = __bfloat16_as_ushort(l);
}

// ---------------------------------------------------------------------------
// Elementwise fp32 -> (bf16 hi, bf16 lo) split, float4-vectorized.
// ---------------------------------------------------------------------------
__global__ __launch_bounds__(256) void split_kernel(
    const float* __restrict__ in, __nv_bfloat16* __restrict__ hi,
    __nv_bfloat16* __restrict__ lo, int n4)
{
    const int i = blockIdx.x * 256 + threadIdx.x;
    if (i >= n4) return;
    float4 v = ((const float4*)in)[i];
    uint16_t h0,h1,h2,h3,l0,l1,l2,l3;
    split2(v.x,h0,l0); split2(v.y,h1,l1);
    split2(v.z,h2,l2); split2(v.w,h3,l3);
    uint2 uh, ul;
    uh.x = (uint32_t)h0 | ((uint32_t)h1 << 16);
    uh.y = (uint32_t)h2 | ((uint32_t)h3 << 16);
    ul.x = (uint32_t)l0 | ((uint32_t)l1 << 16);
    ul.y = (uint32_t)l2 | ((uint32_t)l3 << 16);
    ((uint2*)hi)[i] = uh;
    ((uint2*)lo)[i] = ul;
}

// ---------------------------------------------------------------------------
// Tensor-core GEMM, pre-split bf16 inputs, cp.async double-buffered.
// C = Ah@Bh + Ah@Bl + Al@Bh (+bias), fp32 accum/out.
// BM=BN=128, BK=32, 256 thr = 8 warps (4m x 2n), warp tile 32m x 64n.
// __launch_bounds__(256,2): 2 CTAs/SM to hide barrier + MMA-latency stalls.
// ---------------------------------------------------------------------------
#define APAD 40     // A row stride (elements): 80B, 16B-aligned, ldsm conflict-free
#define BPAD 136    // B row stride: 272B
#define A_ELS (128 * APAD)
#define B_ELS (32 * BPAD)
#define STAGE_ELS (2 * A_ELS + 2 * B_ELS)
#define GEMM_SMEM (2 * STAGE_ELS * 2)   // bytes, 2 stages (~74 KB)

template<bool BIAS>
__global__ __launch_bounds__(256, 2) void gemm_pre(
    const __nv_bfloat16* __restrict__ Ah, const __nv_bfloat16* __restrict__ Al,
    const __nv_bfloat16* __restrict__ Bh, const __nv_bfloat16* __restrict__ Bl,
    const float* __restrict__ bias, float* __restrict__ C,
    int M, int N, int K)
{
    extern __shared__ __nv_bfloat16 smem[];

    const int tid  = threadIdx.x;
    const int lane = tid & 31;
    const int warp = tid >> 5;
    const int m_base = (warp & 3) * 32;
    const int n_base = (warp >> 2) * 64;
    const int blockM = blockIdx.y * 128;
    const int blockN = blockIdx.x * 128;

    // per-thread load coords (2 chunks of 16B per array per thread)
    const int aRow0 = tid >> 2, aC0 = (tid & 3) << 3;
    const int aRow1 = (tid + 256) >> 2, aC1 = ((tid + 256) & 3) << 3;
    const int bRow0 = tid >> 4, bC0 = (tid & 15) << 3;
    const int bRow1 = (tid + 256) >> 4, bC1 = ((tid + 256) & 15) << 3;

    float acc[2][8][4];
    #pragma unroll
    for (int i = 0; i < 2; i++)
        #pragma unroll
        for (int j = 0; j < 8; j++)
            #pragma unroll
            for (int q = 0; q < 4; q++) acc[i][j][q] = 0.f;

    auto load_tile = [&](int stage, int k0) {
        __nv_bfloat16* sAh = smem + stage * STAGE_ELS;
        __nv_bfloat16* sAl = sAh + A_ELS;
        __nv_bfloat16* sBh = sAl + A_ELS;
        __nv_bfloat16* sBl = sBh + B_ELS;
        cp16(sAh + aRow0 * APAD + aC0, Ah + (size_t)(blockM + aRow0) * K + k0 + aC0);
        cp16(sAh + aRow1 * APAD + aC1, Ah + (size_t)(blockM + aRow1) * K + k0 + aC1);
        cp16(sAl + aRow0 * APAD + aC0, Al + (size_t)(blockM + aRow0) * K + k0 + aC0);
        cp16(sAl + aRow1 * APAD + aC1, Al + (size_t)(blockM + aRow1) * K + k0 + aC1);
        cp16(sBh + bRow0 * BPAD + bC0, Bh + (size_t)(k0 + bRow0) * N + blockN + bC0);
        cp16(sBh + bRow1 * BPAD + bC1, Bh + (size_t)(k0 + bRow1) * N + blockN + bC1);
        cp16(sBl + bRow0 * BPAD + bC0, Bl + (size_t)(k0 + bRow0) * N + blockN + bC0);
        cp16(sBl + bRow1 * BPAD + bC1, Bl + (size_t)(k0 + bRow1) * N + blockN + bC1);
    };

    const int NT = K >> 5;   // K/32
    load_tile(0, 0);
    cp_commit();

    for (int kt = 0; kt < NT; kt++) {
        if (kt + 1 < NT) {
            load_tile((kt + 1) & 1, (kt + 1) << 5);
            cp_commit();
            cp_wait<1>();
        } else {
            cp_wait<0>();
        }
        __syncthreads();

        const __nv_bfloat16* sAh = smem + (kt & 1) * STAGE_ELS;
        const __nv_bfloat16* sAl = sAh + A_ELS;
        const __nv_bfloat16* sBh = sAl + A_ELS;
        const __nv_bfloat16* sBl = sBh + B_ELS;

        #pragma unroll
        for (int ks = 0; ks < 2; ks++) {
            const int kk = ks * 16;
            uint32_t ah[2][4], al[2][4];
            #pragma unroll
            for (int mf = 0; mf < 2; mf++) {
                const int row = m_base + mf * 16 + (lane & 15);
                const int col = kk + ((lane >> 4) << 3);
                ldsm_x4(ah[mf], sm_u32(sAh + row * APAD + col));
                ldsm_x4(al[mf], sm_u32(sAl + row * APAD + col));
            }
            #pragma unroll
            for (int ng = 0; ng < 4; ng++) {
                const int brow = kk + (lane & 15);
                const int bcol = n_base + ng * 16 + ((lane >> 4) << 3);
                uint32_t bh[4], bl[4];
                ldsm_x4_t(bh, sm_u32(sBh + brow * BPAD + bcol));
                ldsm_x4_t(bl, sm_u32(sBl + brow * BPAD + bcol));
                // Product-type outer, acc inner: same accumulator recurs
                // every 4 MMAs (breaks the HMMA RAW chain).
                #pragma unroll
                for (int p = 0; p < 3; p++) {
                    const uint32_t* ap0 = (p == 2) ? al[0] : ah[0];
                    const uint32_t* ap1 = (p == 2) ? al[1] : ah[1];
                    const uint32_t* bp = (p == 1) ? bl : bh;
                    mma16816(acc[0][ng*2+0], ap0, bp + 0);
                    mma16816(acc[1][ng*2+0], ap1, bp + 0);
                    mma16816(acc[0][ng*2+1], ap0, bp + 2);
                    mma16816(acc[1][ng*2+1], ap1, bp + 2);
                }
            }
        }
        __syncthreads();
    }

    #pragma unroll
    for (int mf = 0; mf < 2; mf++) {
        const int r0 = blockM + m_base + mf * 16 + (lane >> 2);
        #pragma unroll
        for (int nf = 0; nf < 8; nf++) {
            const int cN = blockN + n_base + nf * 8 + (lane & 3) * 2;
            float2 v0 = make_float2(acc[mf][nf][0], acc[mf][nf][1]);
            float2 v1 = make_float2(acc[mf][nf][2], acc[mf][nf][3]);
            if (BIAS) {
                const float b0 = bias[cN], b1 = bias[cN + 1];
                v0.x += b0; v0.y += b1; v1.x += b0; v1.y += b1;
            }
            *(float2*)(C + (size_t)r0 * N + cN) = v0;
            *(float2*)(C + (size_t)(r0 + 8) * N + cN) = v1;
        }
    }
}

// ---------------------------------------------------------------------------
// Spatial attention: one block per (n*t, head). 256 threads, 1 query each.
// Outputs bf16 hi/lo split (feeds GEMM2 directly).
// ---------------------------------------------------------------------------
__global__ __launch_bounds__(256) void spatial_attn(
    const float* __restrict__ qkv,
    __nv_bfloat16* __restrict__ oh, __nv_bfloat16* __restrict__ ol)
{
    extern __shared__ float sm[];
    float* Ks = sm;             // [256][64]
    float* Vs = sm + 256 * 64;  // [256][64]

    const int inst = blockIdx.x;     // 0..255
    const int h = inst & 7;
    const int nt = inst >> 3;        // 0..31
    const int tid = threadIdx.x;     // query index s

    const float* base = qkv + (size_t)nt * SB * THREE_D;

    for (int i = tid; i < 256 * 16; i += 256) {
        const int row = i >> 4;
        const int c4 = (i & 15) << 2;
        const float* rb = base + (size_t)row * THREE_D + h * DH;
        *(float4*)(Ks + row * DH + c4) = *(const float4*)(rb + 1024 + c4);
        *(float4*)(Vs + row * DH + c4) = *(const float4*)(rb + 2048 + c4);
    }

    float q[DH];
    {
        const float* qp = base + (size_t)tid * THREE_D + h * DH;
        #pragma unroll
        for (int d4 = 0; d4 < 16; d4++) {
            float4 t = *(const float4*)(qp + d4 * 4);
            q[d4*4+0] = t.x; q[d4*4+1] = t.y; q[d4*4+2] = t.z; q[d4*4+3] = t.w;
        }
    }
    __syncthreads();

    const float scale = 0.125f;
    float m = -INFINITY, l = 0.f;
    float acc[DH];
    #pragma unroll
    for (int d = 0; d < DH; d++) acc[d] = 0.f;

    for (int j = 0; j < SB; j++) {
        const float* kj = Ks + j * DH;
        float s = 0.f;
        #pragma unroll
        for (int d = 0; d < DH; d++) s = fmaf(q[d], kj[d], s);
        s *= scale;
        const float mn = fmaxf(m, s);
        const float c = __expf(m - mn);
        const float p = __expf(s - mn);
        l = l * c + p;
        m = mn;
        const float* vj = Vs + j * DH;
        #pragma unroll
        for (int d = 0; d < DH; d++) acc[d] = fmaf(acc[d], c, p * vj[d]);
    }

    const float inv = 1.f / l;
    const size_t obase = ((size_t)nt * SB + tid) * DB + h * DH;   // cols [0,512)
    #pragma unroll
    for (int d8 = 0; d8 < 8; d8++) {
        uint4 uh, ul;
        uint16_t hh[8], lt[8];
        #pragma unroll
        for (int e = 0; e < 8; e++)
            split2(acc[d8 * 8 + e] * inv, hh[e], lt[e]);
        uh.x = (uint32_t)hh[0] | ((uint32_t)hh[1] << 16);
        uh.y = (uint32_t)hh[2] | ((uint32_t)hh[3] << 16);
        uh.z = (uint32_t)hh[4] | ((uint32_t)hh[5] << 16);
        uh.w = (uint32_t)hh[6] | ((uint32_t)hh[7] << 16);
        ul.x = (uint32_t)lt[0] | ((uint32_t)lt[1] << 16);
        ul.y = (uint32_t)lt[2] | ((uint32_t)lt[3] << 16);
        ul.z = (uint32_t)lt[4] | ((uint32_t)lt[5] << 16);
        ul.w = (uint32_t)lt[6] | ((uint32_t)lt[7] << 16);
        *(uint4*)(oh + obase + d8 * 8) = uh;
        *(uint4*)(ol + obase + d8 * 8) = ul;
    }
}

// ---------------------------------------------------------------------------
// Temporal attention: one block per (n, s). 128 threads: tid = t*8 + h.
// Outputs bf16 hi/lo split.
// ---------------------------------------------------------------------------
__global__ __launch_bounds__(128) void temporal_attn(
    const float* __restrict__ qkv,
    __nv_bfloat16* __restrict__ oh, __nv_bfloat16* __restrict__ ol)
{
    extern __shared__ float sm[];
    float* Ks = sm;              // [16][512]
    float* Vs = sm + 16 * 512;   // [16][512]

    const int ns = blockIdx.x;
    const int n = ns >> 8;
    const int s = ns & 255;
    const int tid = threadIdx.x;
    const int h = tid & 7;
    const int t = tid >> 3;

    const size_t tstride = (size_t)SB * THREE_D;
    const float* rowbase = qkv + ((size_t)(n * TB) * SB + s) * THREE_D;

    for (int i = tid; i < 16 * 128; i += 128) {
        const int row = i >> 7;
        const int c4 = (i & 127) << 2;
        const float* rb = rowbase + row * tstride;
        *(float4*)(Ks + row * 512 + c4) = *(const float4*)(rb + 1536 + c4);
        *(float4*)(Vs + row * 512 + c4) = *(const float4*)(rb + 2560 + c4);
    }

    float q[DH];
    {
        const float* qp = rowbase + t * tstride + 512 + h * DH;
        #pragma unroll
        for (int d4 = 0; d4 < 16; d4++) {
            float4 v = *(const float4*)(qp + d4 * 4);
            q[d4*4+0] = v.x; q[d4*4+1] = v.y; q[d4*4+2] = v.z; q[d4*4+3] = v.w;
        }
    }
    __syncthreads();

    const float scale = 0.125f;
    float sc[TB];
    float mmax = -INFINITY;
    #pragma unroll
    for (int j = 0; j < TB; j++) {
        const float* kj = Ks + j * 512 + h * DH;
        float d0 = 0.f;
        #pragma unroll
        for (int d = 0; d < DH; d++) d0 = fmaf(q[d], kj[d], d0);
        sc[j] = d0 * scale;
        mmax = fmaxf(mmax, sc[j]);
    }
    float lsum = 0.f;
    #pragma unroll
    for (int j = 0; j < TB; j++) {
        sc[j] = __expf(sc[j] - mmax);
        lsum += sc[j];
    }
    const float inv = 1.f / lsum;

    float acc[DH];
    #pragma unroll
    for (int d = 0; d < DH; d++) acc[d] = 0.f;
    #pragma unroll
    for (int j = 0; j < TB; j++) {
        const float p = sc[j];
        const float* vj = Vs + j * 512 + h * DH;
        #pragma unroll
        for (int d = 0; d < DH; d++) acc[d] = fmaf(p, vj[d], acc[d]);
    }

    const size_t obase = ((size_t)(n * TB + t) * SB + s) * DB + 512 + h * DH;
    #pragma unroll
    for (int d8 = 0; d8 < 8; d8++) {
        uint4 uh, ul;
        uint16_t hh[8], lt[8];
        #pragma unroll
        for (int e = 0; e < 8; e++)
            split2(acc[d8 * 8 + e] * inv, hh[e], lt[e]);
        uh.x = (uint32_t)hh[0] | ((uint32_t)hh[1] << 16);
        uh.y = (uint32_t)hh[2] | ((uint32_t)hh[3] << 16);
        uh.z = (uint32_t)hh[4] | ((uint32_t)hh[5] << 16);
        uh.w = (uint32_t)hh[6] | ((uint32_t)hh[7] << 16);
        ul.x = (uint32_t)lt[0] | ((uint32_t)lt[1] << 16);
        ul.y = (uint32_t)lt[2] | ((uint32_t)lt[3] << 16);
        ul.z = (uint32_t)lt[4] | ((uint32_t)lt[5] << 16);
        ul.w = (uint32_t)lt[6] | ((uint32_t)lt[7] << 16);
        *(uint4*)(oh + obase + d8 * 8) = uh;
        *(uint4*)(ol + obase + d8 * 8) = ul;
    }
}

// ---------------------------------------------------------------------------
extern "C" void kernel_launch(void* const* d_in, const int* in_sizes, int n_in,
                              void* d_out, int out_size)
{
    const float* x     = (const float*)d_in[0];  // [2,16,256,1024]
    const float* Wqkv  = (const float*)d_in[1];  // [1024,3072]
    const float* Wproj = (const float*)d_in[2];  // [1024,1024]
    const float* bproj = (const float*)d_in[3];  // [1024]
    float* out = (float*)d_out;

    float *qkv_ptr;
    __nv_bfloat16 *xh, *xl, *wqh, *wql, *wph, *wpl, *ah, *al;
    cudaGetSymbolAddress((void**)&qkv_ptr, g_qkv);
    cudaGetSymbolAddress((void**)&xh, g_xh);
    cudaGetSymbolAddress((void**)&xl, g_xl);
    cudaGetSymbolAddress((void**)&wqh, g_wqh);
    cudaGetSymbolAddress((void**)&wql, g_wql);
    cudaGetSymbolAddress((void**)&wph, g_wph);
    cudaGetSymbolAddress((void**)&wpl, g_wpl);
    cudaGetSymbolAddress((void**)&ah, g_ah);
    cudaGetSymbolAddress((void**)&al, g_al);

    cudaFuncSetAttribute(gemm_pre<false>,
        cudaFuncAttributeMaxDynamicSharedMemorySize, GEMM_SMEM);
    cudaFuncSetAttribute(gemm_pre<true>,
        cudaFuncAttributeMaxDynamicSharedMemorySize, GEMM_SMEM);
    cudaFuncSetAttribute(spatial_attn,
        cudaFuncAttributeMaxDynamicSharedMemorySize, 2 * 256 * DH * 4);
    cudaFuncSetAttribute(temporal_attn,
        cudaFuncAttributeMaxDynamicSharedMemorySize, 2 * 16 * 512 * 4);

    // 0) pre-split inputs to bf16 hi/lo
    {
        int n4x = ROWS * DB / 4;
        split_kernel<<<n4x / 256, 256>>>(x, xh, xl, n4x);
        int n4q = DB * THREE_D / 4;
        split_kernel<<<n4q / 256, 256>>>(Wqkv, wqh, wql, n4q);
        int n4p = DB * DB / 4;
        split_kernel<<<n4p / 256, 256>>>(Wproj, wph, wpl, n4p);
    }

    // 1) qkv = x @ Wqkv : [8192,1024] x [1024,3072]
    {
        dim3 grid(THREE_D / 128, ROWS / 128);
        gemm_pre<false><<<grid, 256, GEMM_SMEM>>>(xh, xl, wqh, wql, nullptr,
                                                  qkv_ptr, ROWS, THREE_D, DB);
    }

    // 2) spatial attention: 256 instances (n*t, head) -> bf16 hi/lo
    spatial_attn<<<NB * TB * HEADS, 256, 2 * 256 * DH * 4>>>(qkv_ptr, ah, al);

    // 3) temporal attention: 512 blocks (n, s) -> bf16 hi/lo
    temporal_attn<<<NB * SB, 128, 2 * 16 * 512 * 4>>>(qkv_ptr, ah, al);

    // 4) out = attn @ Wproj + bproj : [8192,1024] x [1024,1024]
    {
        dim3 grid(DB / 128, ROWS / 128);
        gemm_pre<true><<<grid, 256, GEMM_SMEM>>>(ah, al, wph, wpl, bproj,
                                                 out, ROWS, DB, DB);
    }
}

// round 10
// speedup vs baseline: 2.4084x; 1.0103x over previous
#include <cuda_runtime.h>
#include <cuda_bf16.h>
#include <math.h>
#include <stdint.h>

// Problem: x[N=2,T=16,S=256,D=1024]
// qkv = x @ Wqkv[1024,3072]; heads=8, Dh=64, scale=0.125
// spatial attn over S per (n,t,h); temporal attn over T per (n,s,h)
// out = concat(x_s, x_t) @ Wproj + bproj

#define NB 2
#define TB 16
#define SB 256
#define DB 1024
#define ROWS (NB*TB*SB)      // 8192
#define THREE_D (3*DB)       // 3072
#define HEADS 8
#define DH 64

// Scratch (device globals; allocation-free per harness rules)
__device__ float g_qkv[(size_t)ROWS * THREE_D];          // fp32 qkv, ~100.7MB
__device__ __nv_bfloat16 g_xh[(size_t)ROWS * DB];        // x hi/lo
__device__ __nv_bfloat16 g_xl[(size_t)ROWS * DB];
__device__ __nv_bfloat16 g_wqh[(size_t)DB * THREE_D];    // Wqkv hi/lo
__device__ __nv_bfloat16 g_wql[(size_t)DB * THREE_D];
__device__ __nv_bfloat16 g_wph[(size_t)DB * DB];         // Wproj hi/lo
__device__ __nv_bfloat16 g_wpl[(size_t)DB * DB];
__device__ __nv_bfloat16 g_ah[(size_t)ROWS * DB];        // attn out hi/lo
__device__ __nv_bfloat16 g_al[(size_t)ROWS * DB];

// ---------------------------------------------------------------------------
// helpers
// ---------------------------------------------------------------------------
__device__ __forceinline__ uint32_t sm_u32(const void* p) {
    return (uint32_t)__cvta_generic_to_shared(p);
}
__device__ __forceinline__ void cp16(void* sdst, const void* gsrc) {
    asm volatile("cp.async.cg.shared.global [%0], [%1], 16;\n"
                 :: "r"(sm_u32(sdst)), "l"(gsrc));
}
__device__ __forceinline__ void cp_commit() {
    asm volatile("cp.async.commit_group;\n");
}
template<int NPEND>
__device__ __forceinline__ void cp_wait() {
    asm volatile("cp.async.wait_group %0;\n" :: "n"(NPEND));
}
__device__ __forceinline__ void ldsm_x4(uint32_t* r, uint32_t addr) {
    asm volatile("ldmatrix.sync.aligned.m8n8.x4.shared.b16 {%0,%1,%2,%3}, [%4];"
                 : "=r"(r[0]), "=r"(r[1]), "=r"(r[2]), "=r"(r[3]) : "r"(addr));
}
__device__ __forceinline__ void ldsm_x4_t(uint32_t* r, uint32_t addr) {
    asm volatile("ldmatrix.sync.aligned.m8n8.x4.trans.shared.b16 {%0,%1,%2,%3}, [%4];"
                 : "=r"(r[0]), "=r"(r[1]), "=r"(r[2]), "=r"(r[3]) : "r"(addr));
}
__device__ __forceinline__ void mma16816(float* c, const uint32_t* a,
                                         const uint32_t* b) {
    asm volatile(
        "mma.sync.aligned.m16n8k16.row.col.f32.bf16.bf16.f32 "
        "{%0,%1,%2,%3}, {%4,%5,%6,%7}, {%8,%9}, {%0,%1,%2,%3};"
        : "+f"(c[0]), "+f"(c[1]), "+f"(c[2]), "+f"(c[3])
        : "r"(a[0]), "r"(a[1]), "r"(a[2]), "r"(a[3]), "r"(b[0]), "r"(b[1]));
}
__device__ __forceinline__ void split2(float v, uint16_t& hi, uint16_t& lo) {
    __nv_bfloat16 h = __float2bfloat16(v);
    __nv_bfloat16 l = __float2bfloat16(v - __bfloat162float(h));
    hi = __bfloat16_as_ushort(h);
    lo = __bfloat16_as_ushort(l);
}

// ---------------------------------------------------------------------------
// Elementwise fp32 -> (bf16 hi, bf16 lo) split, float4-vectorized.
// ---------------------------------------------------------------------------
__global__ __launch_bounds__(256) void split_kernel(
    const float* __restrict__ in, __nv_bfloat16* __restrict__ hi,
    __nv_bfloat16* __restrict__ lo, int n4)
{
    const int i = blockIdx.x * 256 + threadIdx.x;
    if (i >= n4) return;
    float4 v = ((const float4*)in)[i];
    uint16_t h0,h1,h2,h3,l0,l1,l2,l3;
    split2(v.x,h0,l0); split2(v.y,h1,l1);
    split2(v.z,h2,l2); split2(v.w,h3,l3);
    uint2 uh, ul;
    uh.x = (uint32_t)h0 | ((uint32_t)h1 << 16);
    uh.y = (uint32_t)h2 | ((uint32_t)h3 << 16);
    ul.x = (uint32_t)l0 | ((uint32_t)l1 << 16);
    ul.y = (uint32_t)l2 | ((uint32_t)l3 << 16);
    ((uint2*)hi)[i] = uh;
    ((uint2*)lo)[i] = ul;
}

// ---------------------------------------------------------------------------
// Tensor-core GEMM, pre-split bf16 inputs, 3-stage cp.async pipeline,
// ONE __syncthreads per k-tile (stage (kt+2)%3 == (kt-1)%3, drained by
// the top-of-loop barrier before its overwrite is issued).
// C = Ah@Bh + Ah@Bl + Al@Bh (+bias), fp32 accum/out.
// BM=BN=128, BK=32, 256 thr = 8 warps (4m x 2n). 2 CTAs/SM.
// ---------------------------------------------------------------------------
#define APAD 40     // A row stride (elements): 80B
#define BPAD 136    // B row stride: 272B
#define A_ELS (128 * APAD)
#define B_ELS (32 * BPAD)
#define STAGE_ELS (2 * A_ELS + 2 * B_ELS)
#define NSTAGE 3
#define GEMM_SMEM (NSTAGE * STAGE_ELS * 2)   // 113,664 B; x2 CTAs = 227 KB

template<bool BIAS>
__global__ __launch_bounds__(256, 2) void gemm_pre(
    const __nv_bfloat16* __restrict__ Ah, const __nv_bfloat16* __restrict__ Al,
    const __nv_bfloat16* __restrict__ Bh, const __nv_bfloat16* __restrict__ Bl,
    const float* __restrict__ bias, float* __restrict__ C,
    int M, int N, int K)
{
    extern __shared__ __nv_bfloat16 smem[];

    const int tid  = threadIdx.x;
    const int lane = tid & 31;
    const int warp = tid >> 5;
    const int m_base = (warp & 3) * 32;
    const int n_base = (warp >> 2) * 64;
    const int blockM = blockIdx.y * 128;
    const int blockN = blockIdx.x * 128;

    const int aRow0 = tid >> 2, aC0 = (tid & 3) << 3;
    const int aRow1 = (tid + 256) >> 2, aC1 = ((tid + 256) & 3) << 3;
    const int bRow0 = tid >> 4, bC0 = (tid & 15) << 3;
    const int bRow1 = (tid + 256) >> 4, bC1 = ((tid + 256) & 15) << 3;

    float acc[2][8][4];
    #pragma unroll
    for (int i = 0; i < 2; i++)
        #pragma unroll
        for (int j = 0; j < 8; j++)
            #pragma unroll
            for (int q = 0; q < 4; q++) acc[i][j][q] = 0.f;

    auto load_tile = [&](int stage, int k0) {
        __nv_bfloat16* sAh = smem + stage * STAGE_ELS;
        __nv_bfloat16* sAl = sAh + A_ELS;
        __nv_bfloat16* sBh = sAl + A_ELS;
        __nv_bfloat16* sBl = sBh + B_ELS;
        cp16(sAh + aRow0 * APAD + aC0, Ah + (size_t)(blockM + aRow0) * K + k0 + aC0);
        cp16(sAh + aRow1 * APAD + aC1, Ah + (size_t)(blockM + aRow1) * K + k0 + aC1);
        cp16(sAl + aRow0 * APAD + aC0, Al + (size_t)(blockM + aRow0) * K + k0 + aC0);
        cp16(sAl + aRow1 * APAD + aC1, Al + (size_t)(blockM + aRow1) * K + k0 + aC1);
        cp16(sBh + bRow0 * BPAD + bC0, Bh + (size_t)(k0 + bRow0) * N + blockN + bC0);
        cp16(sBh + bRow1 * BPAD + bC1, Bh + (size_t)(k0 + bRow1) * N + blockN + bC1);
        cp16(sBl + bRow0 * BPAD + bC0, Bl + (size_t)(k0 + bRow0) * N + blockN + bC0);
        cp16(sBl + bRow1 * BPAD + bC1, Bl + (size_t)(k0 + bRow1) * N + blockN + bC1);
    };

    const int NT = K >> 5;   // K/32
    load_tile(0, 0);
    cp_commit();
    load_tile(1, 32);
    cp_commit();

    int stage = 0;
    for (int kt = 0; kt < NT; kt++) {
        if (kt < NT - 1) cp_wait<1>(); else cp_wait<0>();
        __syncthreads();   // stage kt ready; also: all warps done reading (kt-1)%3

        if (kt + 2 < NT) {
            int st2 = stage + 2; if (st2 >= NSTAGE) st2 -= NSTAGE;
            load_tile(st2, (kt + 2) << 5);
            cp_commit();
        }

        const __nv_bfloat16* sAh = smem + stage * STAGE_ELS;
        const __nv_bfloat16* sAl = sAh + A_ELS;
        const __nv_bfloat16* sBh = sAl + A_ELS;
        const __nv_bfloat16* sBl = sBh + B_ELS;

        #pragma unroll
        for (int ks = 0; ks < 2; ks++) {
            const int kk = ks * 16;
            uint32_t ah[2][4], al[2][4];
            #pragma unroll
            for (int mf = 0; mf < 2; mf++) {
                const int row = m_base + mf * 16 + (lane & 15);
                const int col = kk + ((lane >> 4) << 3);
                ldsm_x4(ah[mf], sm_u32(sAh + row * APAD + col));
                ldsm_x4(al[mf], sm_u32(sAl + row * APAD + col));
            }
            #pragma unroll
            for (int ng = 0; ng < 4; ng++) {
                const int brow = kk + (lane & 15);
                const int bcol = n_base + ng * 16 + ((lane >> 4) << 3);
                uint32_t bh[4], bl[4];
                ldsm_x4_t(bh, sm_u32(sBh + brow * BPAD + bcol));
                ldsm_x4_t(bl, sm_u32(sBl + brow * BPAD + bcol));
                #pragma unroll
                for (int p = 0; p < 3; p++) {
                    const uint32_t* ap0 = (p == 2) ? al[0] : ah[0];
                    const uint32_t* ap1 = (p == 2) ? al[1] : ah[1];
                    const uint32_t* bp = (p == 1) ? bl : bh;
                    mma16816(acc[0][ng*2+0], ap0, bp + 0);
                    mma16816(acc[1][ng*2+0], ap1, bp + 0);
                    mma16816(acc[0][ng*2+1], ap0, bp + 2);
                    mma16816(acc[1][ng*2+1], ap1, bp + 2);
                }
            }
        }
        if (++stage >= NSTAGE) stage = 0;
    }

    #pragma unroll
    for (int mf = 0; mf < 2; mf++) {
        const int r0 = blockM + m_base + mf * 16 + (lane >> 2);
        #pragma unroll
        for (int nf = 0; nf < 8; nf++) {
            const int cN = blockN + n_base + nf * 8 + (lane & 3) * 2;
            float2 v0 = make_float2(acc[mf][nf][0], acc[mf][nf][1]);
            float2 v1 = make_float2(acc[mf][nf][2], acc[mf][nf][3]);
            if (BIAS) {
                const float b0 = bias[cN], b1 = bias[cN + 1];
                v0.x += b0; v0.y += b1; v1.x += b0; v1.y += b1;
            }
            *(float2*)(C + (size_t)r0 * N + cN) = v0;
            *(float2*)(C + (size_t)(r0 + 8) * N + cN) = v1;
        }
    }
}

// ---------------------------------------------------------------------------
// Spatial attention: one block per (n*t, head). 256 threads, 1 query each.
// Key-tiles of 8 with DEFERRED rescale: 1 FMA/elem/key accumulate + one
// rescale per 8 keys (instead of 2 FMA/elem/key).
// Outputs bf16 hi/lo split.
// ---------------------------------------------------------------------------
__global__ __launch_bounds__(256) void spatial_attn(
    const float* __restrict__ qkv,
    __nv_bfloat16* __restrict__ oh, __nv_bfloat16* __restrict__ ol)
{
    extern __shared__ float sm[];
    float* Ks = sm;             // [256][64]
    float* Vs = sm + 256 * 64;  // [256][64]

    const int inst = blockIdx.x;     // 0..255
    const int h = inst & 7;
    const int nt = inst >> 3;        // 0..31
    const int tid = threadIdx.x;     // query index s

    const float* base = qkv + (size_t)nt * SB * THREE_D;

    for (int i = tid; i < 256 * 16; i += 256) {
        const int row = i >> 4;
        const int c4 = (i & 15) << 2;
        const float* rb = base + (size_t)row * THREE_D + h * DH;
        *(float4*)(Ks + row * DH + c4) = *(const float4*)(rb + 1024 + c4);
        *(float4*)(Vs + row * DH + c4) = *(const float4*)(rb + 2048 + c4);
    }

    float q[DH];
    {
        const float* qp = base + (size_t)tid * THREE_D + h * DH;
        #pragma unroll
        for (int d4 = 0; d4 < 16; d4++) {
            float4 t = *(const float4*)(qp + d4 * 4);
            q[d4*4+0] = t.x; q[d4*4+1] = t.y; q[d4*4+2] = t.z; q[d4*4+3] = t.w;
        }
    }
    __syncthreads();

    const float scale = 0.125f;
    float m = -INFINITY, l = 0.f;
    float acc[DH];
    #pragma unroll
    for (int d = 0; d < DH; d++) acc[d] = 0.f;

    for (int jt = 0; jt < SB; jt += 8) {
        // scores for 8 keys (2-accumulator ILP dot)
        float s8[8];
        float tmax = -INFINITY;
        #pragma unroll
        for (int u = 0; u < 8; u++) {
            const float* kj = Ks + (jt + u) * DH;
            float d0 = 0.f, d1 = 0.f;
            #pragma unroll
            for (int d = 0; d < DH; d += 2) {
                d0 = fmaf(q[d],     kj[d],     d0);
                d1 = fmaf(q[d + 1], kj[d + 1], d1);
            }
            s8[u] = (d0 + d1) * scale;
            tmax = fmaxf(tmax, s8[u]);
        }
        // one rescale per tile
        const float mn = fmaxf(m, tmax);
        const float c = __expf(m - mn);   // 0 on first tile (m=-inf)
        l *= c;
        #pragma unroll
        for (int d = 0; d < DH; d++) acc[d] *= c;
        m = mn;
        // accumulate 8 keys at 1 FMA/elem
        #pragma unroll
        for (int u = 0; u < 8; u++) {
            const float p = __expf(s8[u] - m);
            l += p;
            const float* vj = Vs + (jt + u) * DH;
            #pragma unroll
            for (int d = 0; d < DH; d++) acc[d] = fmaf(p, vj[d], acc[d]);
        }
    }

    const float inv = 1.f / l;
    const size_t obase = ((size_t)nt * SB + tid) * DB + h * DH;   // cols [0,512)
    #pragma unroll
    for (int d8 = 0; d8 < 8; d8++) {
        uint4 uh, ul;
        uint16_t hh[8], lt[8];
        #pragma unroll
        for (int e = 0; e < 8; e++)
            split2(acc[d8 * 8 + e] * inv, hh[e], lt[e]);
        uh.x = (uint32_t)hh[0] | ((uint32_t)hh[1] << 16);
        uh.y = (uint32_t)hh[2] | ((uint32_t)hh[3] << 16);
        uh.z = (uint32_t)hh[4] | ((uint32_t)hh[5] << 16);
        uh.w = (uint32_t)hh[6] | ((uint32_t)hh[7] << 16);
        ul.x = (uint32_t)lt[0] | ((uint32_t)lt[1] << 16);
        ul.y = (uint32_t)lt[2] | ((uint32_t)lt[3] << 16);
        ul.z = (uint32_t)lt[4] | ((uint32_t)lt[5] << 16);
        ul.w = (uint32_t)lt[6] | ((uint32_t)lt[7] << 16);
        *(uint4*)(oh + obase + d8 * 8) = uh;
        *(uint4*)(ol + obase + d8 * 8) = ul;
    }
}

// ---------------------------------------------------------------------------
// Temporal attention: one block per (n, s). 128 threads: tid = t*8 + h.
// Outputs bf16 hi/lo split.
// ---------------------------------------------------------------------------
__global__ __launch_bounds__(128) void temporal_attn(
    const float* __restrict__ qkv,
    __nv_bfloat16* __restrict__ oh, __nv_bfloat16* __restrict__ ol)
{
    extern __shared__ float sm[];
    float* Ks = sm;              // [16][512]
    float* Vs = sm + 16 * 512;   // [16][512]

    const int ns = blockIdx.x;
    const int n = ns >> 8;
    const int s = ns & 255;
    const int tid = threadIdx.x;
    const int h = tid & 7;
    const int t = tid >> 3;

    const size_t tstride = (size_t)SB * THREE_D;
    const float* rowbase = qkv + ((size_t)(n * TB) * SB + s) * THREE_D;

    for (int i = tid; i < 16 * 128; i += 128) {
        const int row = i >> 7;
        const int c4 = (i & 127) << 2;
        const float* rb = rowbase + row * tstride;
        *(float4*)(Ks + row * 512 + c4) = *(const float4*)(rb + 1536 + c4);
        *(float4*)(Vs + row * 512 + c4) = *(const float4*)(rb + 2560 + c4);
    }

    float q[DH];
    {
        const float* qp = rowbase + t * tstride + 512 + h * DH;
        #pragma unroll
        for (int d4 = 0; d4 < 16; d4++) {
            float4 v = *(const float4*)(qp + d4 * 4);
            q[d4*4+0] = v.x; q[d4*4+1] = v.y; q[d4*4+2] = v.z; q[d4*4+3] = v.w;
        }
    }
    __syncthreads();

    const float scale = 0.125f;
    float sc[TB];
    float mmax = -INFINITY;
    #pragma unroll
    for (int j = 0; j < TB; j++) {
        const float* kj = Ks + j * 512 + h * DH;
        float d0 = 0.f, d1 = 0.f;
        #pragma unroll
        for (int d = 0; d < DH; d += 2) {
            d0 = fmaf(q[d],     kj[d],     d0);
            d1 = fmaf(q[d + 1], kj[d + 1], d1);
        }
        sc[j] = (d0 + d1) * scale;
        mmax = fmaxf(mmax, sc[j]);
    }
    float lsum = 0.f;
    #pragma unroll
    for (int j = 0; j < TB; j++) {
        sc[j] = __expf(sc[j] - mmax);
        lsum += sc[j];
    }
    const float inv = 1.f / lsum;

    float acc[DH];
    #pragma unroll
    for (int d = 0; d < DH; d++) acc[d] = 0.f;
    #pragma unroll
    for (int j = 0; j < TB; j++) {
        const float p = sc[j];
        const float* vj = Vs + j * 512 + h * DH;
        #pragma unroll
        for (int d = 0; d < DH; d++) acc[d] = fmaf(p, vj[d], acc[d]);
    }

    const size_t obase = ((size_t)(n * TB + t) * SB + s) * DB + 512 + h * DH;
    #pragma unroll
    for (int d8 = 0; d8 < 8; d8++) {
        uint4 uh, ul;
        uint16_t hh[8], lt[8];
        #pragma unroll
        for (int e = 0; e < 8; e++)
            split2(acc[d8 * 8 + e] * inv, hh[e], lt[e]);
        uh.x = (uint32_t)hh[0] | ((uint32_t)hh[1] << 16);
        uh.y = (uint32_t)hh[2] | ((uint32_t)hh[3] << 16);
        uh.z = (uint32_t)hh[4] | ((uint32_t)hh[5] << 16);
        uh.w = (uint32_t)hh[6] | ((uint32_t)hh[7] << 16);
        ul.x = (uint32_t)lt[0] | ((uint32_t)lt[1] << 16);
        ul.y = (uint32_t)lt[2] | ((uint32_t)lt[3] << 16);
        ul.z = (uint32_t)lt[4] | ((uint32_t)lt[5] << 16);
        ul.w = (uint32_t)lt[6] | ((uint32_t)lt[7] << 16);
        *(uint4*)(oh + obase + d8 * 8) = uh;
        *(uint4*)(ol + obase + d8 * 8) = ul;
    }
}

// ---------------------------------------------------------------------------
extern "C" void kernel_launch(void* const* d_in, const int* in_sizes, int n_in,
                              void* d_out, int out_size)
{
    const float* x     = (const float*)d_in[0];  // [2,16,256,1024]
    const float* Wqkv  = (const float*)d_in[1];  // [1024,3072]
    const float* Wproj = (const float*)d_in[2];  // [1024,1024]
    const float* bproj = (const float*)d_in[3];  // [1024]
    float* out = (float*)d_out;

    float *qkv_ptr;
    __nv_bfloat16 *xh, *xl, *wqh, *wql, *wph, *wpl, *ah, *al;
    cudaGetSymbolAddress((void**)&qkv_ptr, g_qkv);
    cudaGetSymbolAddress((void**)&xh, g_xh);
    cudaGetSymbolAddress((void**)&xl, g_xl);
    cudaGetSymbolAddress((void**)&wqh, g_wqh);
    cudaGetSymbolAddress((void**)&wql, g_wql);
    cudaGetSymbolAddress((void**)&wph, g_wph);
    cudaGetSymbolAddress((void**)&wpl, g_wpl);
    cudaGetSymbolAddress((void**)&ah, g_ah);
    cudaGetSymbolAddress((void**)&al, g_al);

    cudaFuncSetAttribute(gemm_pre<false>,
        cudaFuncAttributeMaxDynamicSharedMemorySize, GEMM_SMEM);
    cudaFuncSetAttribute(gemm_pre<true>,
        cudaFuncAttributeMaxDynamicSharedMemorySize, GEMM_SMEM);
    cudaFuncSetAttribute(spatial_attn,
        cudaFuncAttributeMaxDynamicSharedMemorySize, 2 * 256 * DH * 4);
    cudaFuncSetAttribute(temporal_attn,
        cudaFuncAttributeMaxDynamicSharedMemorySize, 2 * 16 * 512 * 4);

    // 0) pre-split inputs to bf16 hi/lo
    {
        int n4x = ROWS * DB / 4;
        split_kernel<<<n4x / 256, 256>>>(x, xh, xl, n4x);
        int n4q = DB * THREE_D / 4;
        split_kernel<<<n4q / 256, 256>>>(Wqkv, wqh, wql, n4q);
        int n4p = DB * DB / 4;
        split_kernel<<<n4p / 256, 256>>>(Wproj, wph, wpl, n4p);
    }

    // 1) qkv = x @ Wqkv : [8192,1024] x [1024,3072]
    {
        dim3 grid(THREE_D / 128, ROWS / 128);
        gemm_pre<false><<<grid, 256, GEMM_SMEM>>>(xh, xl, wqh, wql, nullptr,
                                                  qkv_ptr, ROWS, THREE_D, DB);
    }

    // 2) spatial attention: 256 instances (n*t, head) -> bf16 hi/lo
    spatial_attn<<<NB * TB * HEADS, 256, 2 * 256 * DH * 4>>>(qkv_ptr, ah, al);

    // 3) temporal attention: 512 blocks (n, s) -> bf16 hi/lo
    temporal_attn<<<NB * SB, 128, 2 * 16 * 512 * 4>>>(qkv_ptr, ah, al);

    // 4) out = attn @ Wproj + bproj : [8192,1024] x [1024,1024]
    {
        dim3 grid(DB / 128, ROWS / 128);
        gemm_pre<true><<<grid, 256, GEMM_SMEM>>>(ah, al, wph, wpl, bproj,
                                                 out, ROWS, DB, DB);
    }
}

// round 12
// speedup vs baseline: 2.4742x; 1.0273x over previous
#include <cuda_runtime.h>
#include <cuda_bf16.h>
#include <math.h>
#include <stdint.h>

// Problem: x[N=2,T=16,S=256,D=1024]
// qkv = x @ Wqkv[1024,3072]; heads=8, Dh=64, scale=0.125
// spatial attn over S per (n,t,h); temporal attn over T per (n,s,h)
// out = concat(x_s, x_t) @ Wproj + bproj

#define NB 2
#define TB 16
#define SB 256
#define DB 1024
#define ROWS (NB*TB*SB)      // 8192
#define THREE_D (3*DB)       // 3072
#define HEADS 8
#define DH 64

// Scratch (device globals; allocation-free per harness rules)
__device__ float g_qkv[(size_t)ROWS * THREE_D];          // fp32 qkv, ~100.7MB
__device__ __nv_bfloat16 g_xh[(size_t)ROWS * DB];        // x hi/lo
__device__ __nv_bfloat16 g_xl[(size_t)ROWS * DB];
__device__ __nv_bfloat16 g_wqh[(size_t)DB * THREE_D];    // Wqkv hi/lo
__device__ __nv_bfloat16 g_wql[(size_t)DB * THREE_D];
__device__ __nv_bfloat16 g_wph[(size_t)DB * DB];         // Wproj hi/lo
__device__ __nv_bfloat16 g_wpl[(size_t)DB * DB];
__device__ __nv_bfloat16 g_ah[(size_t)ROWS * DB];        // attn out hi/lo
__device__ __nv_bfloat16 g_al[(size_t)ROWS * DB];

// ---------------------------------------------------------------------------
// helpers
// ---------------------------------------------------------------------------
typedef unsigned long long u64t;

__device__ __forceinline__ uint32_t sm_u32(const void* p) {
    return (uint32_t)__cvta_generic_to_shared(p);
}
__device__ __forceinline__ void cp16(void* sdst, const void* gsrc) {
    asm volatile("cp.async.cg.shared.global [%0], [%1], 16;\n"
                 :: "r"(sm_u32(sdst)), "l"(gsrc));
}
__device__ __forceinline__ void cp_commit() {
    asm volatile("cp.async.commit_group;\n");
}
template<int NPEND>
__device__ __forceinline__ void cp_wait() {
    asm volatile("cp.async.wait_group %0;\n" :: "n"(NPEND));
}
__device__ __forceinline__ void ldsm_x4(uint32_t* r, uint32_t addr) {
    asm volatile("ldmatrix.sync.aligned.m8n8.x4.shared.b16 {%0,%1,%2,%3}, [%4];"
                 : "=r"(r[0]), "=r"(r[1]), "=r"(r[2]), "=r"(r[3]) : "r"(addr));
}
__device__ __forceinline__ void ldsm_x4_t(uint32_t* r, uint32_t addr) {
    asm volatile("ldmatrix.sync.aligned.m8n8.x4.trans.shared.b16 {%0,%1,%2,%3}, [%4];"
                 : "=r"(r[0]), "=r"(r[1]), "=r"(r[2]), "=r"(r[3]) : "r"(addr));
}
__device__ __forceinline__ void mma16816(float* c, const uint32_t* a,
                                         const uint32_t* b) {
    asm volatile(
        "mma.sync.aligned.m16n8k16.row.col.f32.bf16.bf16.f32 "
        "{%0,%1,%2,%3}, {%4,%5,%6,%7}, {%8,%9}, {%0,%1,%2,%3};"
        : "+f"(c[0]), "+f"(c[1]), "+f"(c[2]), "+f"(c[3])
        : "r"(a[0]), "r"(a[1]), "r"(a[2]), "r"(a[3]), "r"(b[0]), "r"(b[1]));
}
__device__ __forceinline__ void split2(float v, uint16_t& hi, uint16_t& lo) {
    __nv_bfloat16 h = __float2bfloat16(v);
    __nv_bfloat16 l = __float2bfloat16(v - __bfloat162float(h));
    hi = __bfloat16_as_ushort(h);
    lo = __bfloat16_as_ushort(l);
}

// ---- packed f32x2 (Blackwell FFMA2, only reachable via PTX fma.rn.f32x2) ----
__device__ __forceinline__ u64t pack2(float lo, float hi) {
    u64t r; asm("mov.b64 %0, {%1, %2};" : "=l"(r) : "f"(lo), "f"(hi));
    return r;
}
__device__ __forceinline__ void unpack2(u64t v, float& lo, float& hi) {
    asm("mov.b64 {%0, %1}, %2;" : "=f"(lo), "=f"(hi) : "l"(v));
}
__device__ __forceinline__ u64t ffma2(u64t a, u64t b, u64t c) {
    u64t d;
    asm("fma.rn.f32x2 %0, %1, %2, %3;" : "=l"(d) : "l"(a), "l"(b), "l"(c));
    return d;
}

// ---------------------------------------------------------------------------
// Elementwise fp32 -> (bf16 hi, bf16 lo) split, float4-vectorized.
// ---------------------------------------------------------------------------
__global__ __launch_bounds__(256) void split_kernel(
    const float* __restrict__ in, __nv_bfloat16* __restrict__ hi,
    __nv_bfloat16* __restrict__ lo, int n4)
{
    const int i = blockIdx.x * 256 + threadIdx.x;
    if (i >= n4) return;
    float4 v = ((const float4*)in)[i];
    uint16_t h0,h1,h2,h3,l0,l1,l2,l3;
    split2(v.x,h0,l0); split2(v.y,h1,l1);
    split2(v.z,h2,l2); split2(v.w,h3,l3);
    uint2 uh, ul;
    uh.x = (uint32_t)h0 | ((uint32_t)h1 << 16);
    uh.y = (uint32_t)h2 | ((uint32_t)h3 << 16);
    ul.x = (uint32_t)l0 | ((uint32_t)l1 << 16);
    ul.y = (uint32_t)l2 | ((uint32_t)l3 << 16);
    ((uint2*)hi)[i] = uh;
    ((uint2*)lo)[i] = ul;
}

// ---------------------------------------------------------------------------
// Tensor-core GEMM (R9 version, measured 389us/65.3% tensor):
// pre-split bf16 inputs, cp.async 2-stage double buffer.
// C = Ah@Bh + Ah@Bl + Al@Bh (+bias), fp32 accum/out.
// BM=BN=128, BK=32, 256 thr = 8 warps (4m x 2n). 2 CTAs/SM.
// ---------------------------------------------------------------------------
#define APAD 40     // A row stride (elements): 80B
#define BPAD 136    // B row stride: 272B
#define A_ELS (128 * APAD)
#define B_ELS (32 * BPAD)
#define STAGE_ELS (2 * A_ELS + 2 * B_ELS)
#define GEMM_SMEM (2 * STAGE_ELS * 2)   // bytes, 2 stages (~74 KB)

template<bool BIAS>
__global__ __launch_bounds__(256, 2) void gemm_pre(
    const __nv_bfloat16* __restrict__ Ah, const __nv_bfloat16* __restrict__ Al,
    const __nv_bfloat16* __restrict__ Bh, const __nv_bfloat16* __restrict__ Bl,
    const float* __restrict__ bias, float* __restrict__ C,
    int M, int N, int K)
{
    extern __shared__ __nv_bfloat16 smem[];

    const int tid  = threadIdx.x;
    const int lane = tid & 31;
    const int warp = tid >> 5;
    const int m_base = (warp & 3) * 32;
    const int n_base = (warp >> 2) * 64;
    const int blockM = blockIdx.y * 128;
    const int blockN = blockIdx.x * 128;

    const int aRow0 = tid >> 2, aC0 = (tid & 3) << 3;
    const int aRow1 = (tid + 256) >> 2, aC1 = ((tid + 256) & 3) << 3;
    const int bRow0 = tid >> 4, bC0 = (tid & 15) << 3;
    const int bRow1 = (tid + 256) >> 4, bC1 = ((tid + 256) & 15) << 3;

    float acc[2][8][4];
    #pragma unroll
    for (int i = 0; i < 2; i++)
        #pragma unroll
        for (int j = 0; j < 8; j++)
            #pragma unroll
            for (int q = 0; q < 4; q++) acc[i][j][q] = 0.f;

    auto load_tile = [&](int stage, int k0) {
        __nv_bfloat16* sAh = smem + stage * STAGE_ELS;
        __nv_bfloat16* sAl = sAh + A_ELS;
        __nv_bfloat16* sBh = sAl + A_ELS;
        __nv_bfloat16* sBl = sBh + B_ELS;
        cp16(sAh + aRow0 * APAD + aC0, Ah + (size_t)(blockM + aRow0) * K + k0 + aC0);
        cp16(sAh + aRow1 * APAD + aC1, Ah + (size_t)(blockM + aRow1) * K + k0 + aC1);
        cp16(sAl + aRow0 * APAD + aC0, Al + (size_t)(blockM + aRow0) * K + k0 + aC0);
        cp16(sAl + aRow1 * APAD + aC1, Al + (size_t)(blockM + aRow1) * K + k0 + aC1);
        cp16(sBh + bRow0 * BPAD + bC0, Bh + (size_t)(k0 + bRow0) * N + blockN + bC0);
        cp16(sBh + bRow1 * BPAD + bC1, Bh + (size_t)(k0 + bRow1) * N + blockN + bC1);
        cp16(sBl + bRow0 * BPAD + bC0, Bl + (size_t)(k0 + bRow0) * N + blockN + bC0);
        cp16(sBl + bRow1 * BPAD + bC1, Bl + (size_t)(k0 + bRow1) * N + blockN + bC1);
    };

    const int NT = K >> 5;   // K/32
    load_tile(0, 0);
    cp_commit();

    for (int kt = 0; kt < NT; kt++) {
        if (kt + 1 < NT) {
            load_tile((kt + 1) & 1, (kt + 1) << 5);
            cp_commit();
            cp_wait<1>();
        } else {
            cp_wait<0>();
        }
        __syncthreads();

        const __nv_bfloat16* sAh = smem + (kt & 1) * STAGE_ELS;
        const __nv_bfloat16* sAl = sAh + A_ELS;
        const __nv_bfloat16* sBh = sAl + A_ELS;
        const __nv_bfloat16* sBl = sBh + B_ELS;

        #pragma unroll
        for (int ks = 0; ks < 2; ks++) {
            const int kk = ks * 16;
            uint32_t ah[2][4], al[2][4];
            #pragma unroll
            for (int mf = 0; mf < 2; mf++) {
                const int row = m_base + mf * 16 + (lane & 15);
                const int col = kk + ((lane >> 4) << 3);
                ldsm_x4(ah[mf], sm_u32(sAh + row * APAD + col));
                ldsm_x4(al[mf], sm_u32(sAl + row * APAD + col));
            }
            #pragma unroll
            for (int ng = 0; ng < 4; ng++) {
                const int brow = kk + (lane & 15);
                const int bcol = n_base + ng * 16 + ((lane >> 4) << 3);
                uint32_t bh[4], bl[4];
                ldsm_x4_t(bh, sm_u32(sBh + brow * BPAD + bcol));
                ldsm_x4_t(bl, sm_u32(sBl + brow * BPAD + bcol));
                #pragma unroll
                for (int p = 0; p < 3; p++) {
                    const uint32_t* ap0 = (p == 2) ? al[0] : ah[0];
                    const uint32_t* ap1 = (p == 2) ? al[1] : ah[1];
                    const uint32_t* bp = (p == 1) ? bl : bh;
                    mma16816(acc[0][ng*2+0], ap0, bp + 0);
                    mma16816(acc[1][ng*2+0], ap1, bp + 0);
                    mma16816(acc[0][ng*2+1], ap0, bp + 2);
                    mma16816(acc[1][ng*2+1], ap1, bp + 2);
                }
            }
        }
        __syncthreads();
    }

    #pragma unroll
    for (int mf = 0; mf < 2; mf++) {
        const int r0 = blockM + m_base + mf * 16 + (lane >> 2);
        #pragma unroll
        for (int nf = 0; nf < 8; nf++) {
            const int cN = blockN + n_base + nf * 8 + (lane & 3) * 2;
            float2 v0 = make_float2(acc[mf][nf][0], acc[mf][nf][1]);
            float2 v1 = make_float2(acc[mf][nf][2], acc[mf][nf][3]);
            if (BIAS) {
                const float b0 = bias[cN], b1 = bias[cN + 1];
                v0.x += b0; v0.y += b1; v1.x += b0; v1.y += b1;
            }
            *(float2*)(C + (size_t)r0 * N + cN) = v0;
            *(float2*)(C + (size_t)(r0 + 8) * N + cN) = v1;
        }
    }
}

// ---------------------------------------------------------------------------
// Fused attention kernel, 512 blocks x 256 threads.
// Blocks [0,256): spatial — one (n*t, head), 1 query/thread, K/V in 128KB smem,
//   key-tiles of 8 with deferred rescale, packed f32x2 FMA.
// Blocks [256,512): temporal — 2 (n,s) pairs per block (128 threads each),
//   K/V read directly from gmem (L1 covers the 16x reuse across t), f32x2 FMA.
// Outputs bf16 hi/lo split.
// ---------------------------------------------------------------------------
#define ATTN_SMEM (2 * 256 * DH * 4)   // 128KB (spatial branch only)

__device__ __forceinline__ void store_hi_lo(
    __nv_bfloat16* oh, __nv_bfloat16* ol, size_t obase, const u64t* acc2,
    float inv)
{
    #pragma unroll
    for (int d8 = 0; d8 < 8; d8++) {
        uint4 uh, ul;
        uint16_t hh[8], lt[8];
        #pragma unroll
        for (int e2 = 0; e2 < 4; e2++) {
            float a0, a1;
            unpack2(acc2[d8 * 4 + e2], a0, a1);
            split2(a0 * inv, hh[e2*2+0], lt[e2*2+0]);
            split2(a1 * inv, hh[e2*2+1], lt[e2*2+1]);
        }
        uh.x = (uint32_t)hh[0] | ((uint32_t)hh[1] << 16);
        uh.y = (uint32_t)hh[2] | ((uint32_t)hh[3] << 16);
        uh.z = (uint32_t)hh[4] | ((uint32_t)hh[5] << 16);
        uh.w = (uint32_t)hh[6] | ((uint32_t)hh[7] << 16);
        ul.x = (uint32_t)lt[0] | ((uint32_t)lt[1] << 16);
        ul.y = (uint32_t)lt[2] | ((uint32_t)lt[3] << 16);
        ul.z = (uint32_t)lt[4] | ((uint32_t)lt[5] << 16);
        ul.w = (uint32_t)lt[6] | ((uint32_t)lt[7] << 16);
        *(uint4*)(oh + obase + d8 * 8) = uh;
        *(uint4*)(ol + obase + d8 * 8) = ul;
    }
}

__global__ __launch_bounds__(256) void fused_attn(
    const float* __restrict__ qkv,
    __nv_bfloat16* __restrict__ oh, __nv_bfloat16* __restrict__ ol)
{
    extern __shared__ float sm[];
    const int tid = threadIdx.x;
    const float scale = 0.125f;

    if (blockIdx.x < 256) {
        // ---------------- spatial ----------------
        float* Ks = sm;             // [256][64]
        float* Vs = sm + 256 * 64;  // [256][64]
        const int inst = blockIdx.x;
        const int h = inst & 7;
        const int nt = inst >> 3;

        const float* base = qkv + (size_t)nt * SB * THREE_D;

        for (int i = tid; i < 256 * 16; i += 256) {
            const int row = i >> 4;
            const int c4 = (i & 15) << 2;
            const float* rb = base + (size_t)row * THREE_D + h * DH;
            *(float4*)(Ks + row * DH + c4) = *(const float4*)(rb + 1024 + c4);
            *(float4*)(Vs + row * DH + c4) = *(const float4*)(rb + 2048 + c4);
        }

        u64t q2[32];
        {
            const u64t* qp2 = (const u64t*)(base + (size_t)tid * THREE_D + h * DH);
            #pragma unroll
            for (int i = 0; i < 32; i++) q2[i] = qp2[i];
        }
        __syncthreads();

        float m = -INFINITY, l = 0.f;
        u64t acc2[32];
        #pragma unroll
        for (int i = 0; i < 32; i++) acc2[i] = 0ull;

        for (int jt = 0; jt < SB; jt += 8) {
            float s8[8];
            float tmax = -INFINITY;
            #pragma unroll
            for (int u = 0; u < 8; u++) {
                const u64t* kj2 = (const u64t*)(Ks + (jt + u) * DH);
                u64t d2a = 0ull, d2b = 0ull;
                #pragma unroll
                for (int i = 0; i < 32; i += 2) {
                    d2a = ffma2(q2[i],     kj2[i],     d2a);
                    d2b = ffma2(q2[i + 1], kj2[i + 1], d2b);
                }
                float a0, a1, b0, b1;
                unpack2(d2a, a0, a1);
                unpack2(d2b, b0, b1);
                s8[u] = ((a0 + b0) + (a1 + b1)) * scale;
                tmax = fmaxf(tmax, s8[u]);
            }
            const float mn = fmaxf(m, tmax);
            const float c = __expf(m - mn);
            l *= c;
            const u64t cc = pack2(c, c);
            #pragma unroll
            for (int i = 0; i < 32; i++) acc2[i] = ffma2(acc2[i], cc, 0ull);
            m = mn;
            #pragma unroll
            for (int u = 0; u < 8; u++) {
                const float p = __expf(s8[u] - m);
                l += p;
                const u64t pp = pack2(p, p);
                const u64t* vj2 = (const u64t*)(Vs + (jt + u) * DH);
                #pragma unroll
                for (int i = 0; i < 32; i++)
                    acc2[i] = ffma2(pp, vj2[i], acc2[i]);
            }
        }

        const size_t obase = ((size_t)nt * SB + tid) * DB + h * DH;  // cols [0,512)
        store_hi_lo(oh, ol, obase, acc2, 1.f / l);
    } else {
        // ---------------- temporal: 2 (n,s) pairs per block ----------------
        const int pair0 = (blockIdx.x - 256) * 2;
        const int half = tid >> 7;
        const int lt = tid & 127;
        const int ns = pair0 + half;
        const int n = ns >> 8;
        const int s = ns & 255;
        const int h = lt & 7;
        const int t = lt >> 3;

        const size_t tstride = (size_t)SB * THREE_D;
        const float* rowbase = qkv + ((size_t)(n * TB) * SB + s) * THREE_D;

        u64t q2[32];
        {
            const u64t* qp2 = (const u64t*)(rowbase + t * tstride + 512 + h * DH);
            #pragma unroll
            for (int i = 0; i < 32; i++) q2[i] = qp2[i];
        }

        float sc[TB];
        float mmax = -INFINITY;
        #pragma unroll
        for (int j = 0; j < TB; j++) {
            const u64t* kj2 = (const u64t*)(rowbase + j * tstride + 1536 + h * DH);
            u64t d2a = 0ull, d2b = 0ull;
            #pragma unroll
            for (int i = 0; i < 32; i += 2) {
                d2a = ffma2(q2[i],     kj2[i],     d2a);
                d2b = ffma2(q2[i + 1], kj2[i + 1], d2b);
            }
            float a0, a1, b0, b1;
            unpack2(d2a, a0, a1);
            unpack2(d2b, b0, b1);
            sc[j] = ((a0 + b0) + (a1 + b1)) * scale;
            mmax = fmaxf(mmax, sc[j]);
        }
        float lsum = 0.f;
        #pragma unroll
        for (int j = 0; j < TB; j++) {
            sc[j] = __expf(sc[j] - mmax);
            lsum += sc[j];
        }

        u64t acc2[32];
        #pragma unroll
        for (int i = 0; i < 32; i++) acc2[i] = 0ull;
        #pragma unroll
        for (int j = 0; j < TB; j++) {
            const u64t pp = pack2(sc[j], sc[j]);
            const u64t* vj2 = (const u64t*)(rowbase + j * tstride + 2560 + h * DH);
            #pragma unroll
            for (int i = 0; i < 32; i++)
                acc2[i] = ffma2(pp, vj2[i], acc2[i]);
        }

        const size_t obase =
            ((size_t)(n * TB + t) * SB + s) * DB + 512 + h * DH;  // cols [512,1024)
        store_hi_lo(oh, ol, obase, acc2, 1.f / lsum);
    }
}

// ---------------------------------------------------------------------------
extern "C" void kernel_launch(void* const* d_in, const int* in_sizes, int n_in,
                              void* d_out, int out_size)
{
    const float* x     = (const float*)d_in[0];  // [2,16,256,1024]
    const float* Wqkv  = (const float*)d_in[1];  // [1024,3072]
    const float* Wproj = (const float*)d_in[2];  // [1024,1024]
    const float* bproj = (const float*)d_in[3];  // [1024]
    float* out = (float*)d_out;

    float *qkv_ptr;
    __nv_bfloat16 *xh, *xl, *wqh, *wql, *wph, *wpl, *ah, *al;
    cudaGetSymbolAddress((void**)&qkv_ptr, g_qkv);
    cudaGetSymbolAddress((void**)&xh, g_xh);
    cudaGetSymbolAddress((void**)&xl, g_xl);
    cudaGetSymbolAddress((void**)&wqh, g_wqh);
    cudaGetSymbolAddress((void**)&wql, g_wql);
    cudaGetSymbolAddress((void**)&wph, g_wph);
    cudaGetSymbolAddress((void**)&wpl, g_wpl);
    cudaGetSymbolAddress((void**)&ah, g_ah);
    cudaGetSymbolAddress((void**)&al, g_al);

    cudaFuncSetAttribute(gemm_pre<false>,
        cudaFuncAttributeMaxDynamicSharedMemorySize, GEMM_SMEM);
    cudaFuncSetAttribute(gemm_pre<true>,
        cudaFuncAttributeMaxDynamicSharedMemorySize, GEMM_SMEM);
    cudaFuncSetAttribute(fused_attn,
        cudaFuncAttributeMaxDynamicSharedMemorySize, ATTN_SMEM);

    // 0) pre-split inputs to bf16 hi/lo
    {
        int n4x = ROWS * DB / 4;
        split_kernel<<<n4x / 256, 256>>>(x, xh, xl, n4x);
        int n4q = DB * THREE_D / 4;
        split_kernel<<<n4q / 256, 256>>>(Wqkv, wqh, wql, n4q);
        int n4p = DB * DB / 4;
        split_kernel<<<n4p / 256, 256>>>(Wproj, wph, wpl, n4p);
    }

    // 1) qkv = x @ Wqkv : [8192,1024] x [1024,3072]
    {
        dim3 grid(THREE_D / 128, ROWS / 128);
        gemm_pre<false><<<grid, 256, GEMM_SMEM>>>(xh, xl, wqh, wql, nullptr,
                                                  qkv_ptr, ROWS, THREE_D, DB);
    }

    // 2) fused spatial (blocks 0-255) + temporal (blocks 256-511) attention
    fused_attn<<<512, 256, ATTN_SMEM>>>(qkv_ptr, ah, al);

    // 3) out = attn @ Wproj + bproj : [8192,1024] x [1024,1024]
    {
        dim3 grid(DB / 128, ROWS / 128);
        gemm_pre<true><<<grid, 256, GEMM_SMEM>>>(ah, al, wph, wpl, bproj,
                                                 out, ROWS, DB, DB);
    }
}